// round 11
// baseline (speedup 1.0000x reference)
#include <cuda_runtime.h>
#include <cuda_bf16.h>
#include <cstdint>
#include <cstddef>

#define D_MODEL   1024
#define D_INNER   1024
#define NQK       32
#define NV_       32
#define DSTATE    64
#define DCONV     4
#define CHUNK_    128
#define CONV_DIM  5120
#define HEADDIM   32
#define IN_PROJ   6176
#define IN_PROJ_PAD 6272
#define BATCH     2
#define SEQ       8192
#define BT        16384
#define NC_       64

// ---- scratch (device globals) ----
__device__ __align__(16) float g_xbcza[(size_t)BT * IN_PROJ];
__device__ __align__(16) float g_xconv[(size_t)BT * CONV_DIM];
__device__ __align__(16) float g_states[(size_t)BATCH * NC_ * NV_ * HEADDIM * DSTATE];
__device__ __align__(16) float g_prevs [(size_t)BATCH * NC_ * NV_ * HEADDIM * DSTATE];
__device__ __align__(16) float g_acum  [(size_t)BATCH * NC_ * NV_ * CHUNK_];
__device__ __align__(16) float g_dc    [BATCH * NC_ * NV_];
__device__ __align__(16) __nv_bfloat16 g_act_hi[(size_t)BT * 1024];
__device__ __align__(16) __nv_bfloat16 g_act_lo[(size_t)BT * 1024];
__device__ __align__(16) __nv_bfloat16 g_w1_hi [(size_t)IN_PROJ_PAD * 1024];
__device__ __align__(16) __nv_bfloat16 g_w1_lo [(size_t)IN_PROJ_PAD * 1024];
__device__ __align__(16) __nv_bfloat16 g_w2_hi [(size_t)1024 * 1024];
__device__ __align__(16) __nv_bfloat16 g_w2_lo [(size_t)1024 * 1024];

// ===========================================================================
// split-bf16 conversion
// ===========================================================================
__global__ void cvt_split(const float* __restrict__ s,
                          __nv_bfloat16* __restrict__ hi,
                          __nv_bfloat16* __restrict__ lo,
                          int n_real, int n_total)
{
    int i = (blockIdx.x * 256 + threadIdx.x) * 4;
    if (i >= n_total) return;
    __nv_bfloat16 h[4], l[4];
    if (i < n_real) {
        float4 v = *(const float4*)(s + i);
        float a[4] = {v.x, v.y, v.z, v.w};
#pragma unroll
        for (int j = 0; j < 4; j++) {
            h[j] = __float2bfloat16(a[j]);
            l[j] = __float2bfloat16(a[j] - __bfloat162float(h[j]));
        }
    } else {
#pragma unroll
        for (int j = 0; j < 4; j++) { h[j] = __float2bfloat16(0.f); l[j] = h[j]; }
    }
    *(__nv_bfloat162*)(hi + i)     = __nv_bfloat162(h[0], h[1]);
    *(__nv_bfloat162*)(hi + i + 2) = __nv_bfloat162(h[2], h[3]);
    *(__nv_bfloat162*)(lo + i)     = __nv_bfloat162(l[0], l[1]);
    *(__nv_bfloat162*)(lo + i + 2) = __nv_bfloat162(l[2], l[3]);
}

// ===========================================================================
// shared helpers
// ===========================================================================
__device__ __forceinline__ uint32_t smem_u32(const void* p) {
    uint32_t a;
    asm("{ .reg .u64 t; cvta.to.shared.u64 t, %1; cvt.u32.u64 %0, t; }"
        : "=r"(a) : "l"(p));
    return a;
}
__device__ __forceinline__ uint32_t sw128(uint32_t off) {
    return off ^ ((off >> 3) & 0x70);
}
__device__ __forceinline__ void ldmat4(uint32_t& r0, uint32_t& r1,
                                       uint32_t& r2, uint32_t& r3, uint32_t a) {
    asm volatile("ldmatrix.sync.aligned.m8n8.x4.shared.b16 {%0,%1,%2,%3}, [%4];"
                 : "=r"(r0), "=r"(r1), "=r"(r2), "=r"(r3) : "r"(a));
}
__device__ __forceinline__ void mma16816(float* c, const uint32_t* a,
                                         uint32_t b0, uint32_t b1) {
    asm volatile(
        "mma.sync.aligned.m16n8k16.row.col.f32.bf16.bf16.f32 "
        "{%0,%1,%2,%3}, {%4,%5,%6,%7}, {%8,%9}, {%0,%1,%2,%3};"
        : "+f"(c[0]), "+f"(c[1]), "+f"(c[2]), "+f"(c[3])
        : "r"(a[0]), "r"(a[1]), "r"(a[2]), "r"(a[3]), "r"(b0), "r"(b1));
}
__device__ __forceinline__ void cp16(uint32_t dst, const void* src) {
    asm volatile("cp.async.cg.shared.global [%0], [%1], 16;"
                 :: "r"(dst), "l"(src));
}

// ===========================================================================
// HMMA split-bf16 GEMM (NT), cp.async 2-stage pipeline, 512 threads (R9)
// ===========================================================================
__device__ __forceinline__ void load_tile_async512(
    const __nv_bfloat16* __restrict__ g, int row0, int K, int k0,
    uint32_t sbase, int tid)
{
#pragma unroll
    for (int j = 0; j < 2; j++) {
        int u = tid + 512 * j;
        int row = u >> 3, cg = u & 7;
        uint32_t off = (uint32_t)(row * 128 + cg * 16);
        cp16(sbase + sw128(off), g + (size_t)(row0 + row) * K + k0 + cg * 8);
    }
}

#define STAGE_SZ 65536u
#define GEMM_SMEM (2 * 65536)
__global__ __launch_bounds__(512, 1)
void gemm_hmma(const __nv_bfloat16* __restrict__ Ahi,
               const __nv_bfloat16* __restrict__ Alo,
               const __nv_bfloat16* __restrict__ Bhi,
               const __nv_bfloat16* __restrict__ Blo,
               float* __restrict__ C, int K, int Nreal, int ldc)
{
    extern __shared__ char sm[];
    const uint32_t s0 = smem_u32(sm);
    const int tid = threadIdx.x;
    const int wid = tid >> 5, lid = tid & 31;
    const int wm = wid & 3, wn = wid >> 2;
    const int m0 = blockIdx.y * 128, n0 = blockIdx.x * 128;

    float acc[2][4][4];
#pragma unroll
    for (int i = 0; i < 2; i++)
#pragma unroll
        for (int j = 0; j < 4; j++)
#pragma unroll
            for (int q = 0; q < 4; q++) acc[i][j][q] = 0.f;

    const int lrow = lid & 15;
    const int lkb  = (lid >> 4) * 16;
    const int NKC = K >> 6;

    {
        uint32_t base = s0;
        load_tile_async512(Ahi, m0, K, 0, base,             tid);
        load_tile_async512(Alo, m0, K, 0, base + 16384,     tid);
        load_tile_async512(Bhi, n0, K, 0, base + 32768,     tid);
        load_tile_async512(Blo, n0, K, 0, base + 49152,     tid);
        asm volatile("cp.async.commit_group;");
    }

    for (int kc = 0; kc < NKC; kc++) {
        if (kc + 1 < NKC) {
            uint32_t base = s0 + ((kc + 1) & 1) * STAGE_SZ;
            int k0 = (kc + 1) << 6;
            load_tile_async512(Ahi, m0, K, k0, base,         tid);
            load_tile_async512(Alo, m0, K, k0, base + 16384, tid);
            load_tile_async512(Bhi, n0, K, k0, base + 32768, tid);
            load_tile_async512(Blo, n0, K, k0, base + 49152, tid);
            asm volatile("cp.async.commit_group;");
            asm volatile("cp.async.wait_group 1;");
        } else {
            asm volatile("cp.async.wait_group 0;");
        }
        __syncthreads();

        const uint32_t sAH = s0 + (kc & 1) * STAGE_SZ;
        const uint32_t sAL = sAH + 16384;
        const uint32_t sBH = sAH + 32768;
        const uint32_t sBL = sAH + 49152;
#pragma unroll
        for (int ks = 0; ks < 4; ks++) {
            const int kb = ks * 32 + lkb;
            uint32_t bh[2][4], bl[2][4];
#pragma unroll
            for (int g2 = 0; g2 < 2; g2++) {
                uint32_t off = (uint32_t)((wn * 32 + g2 * 16 + lrow) * 128 + kb);
                ldmat4(bh[g2][0], bh[g2][1], bh[g2][2], bh[g2][3], sBH + sw128(off));
                ldmat4(bl[g2][0], bl[g2][1], bl[g2][2], bl[g2][3], sBL + sw128(off));
            }
#pragma unroll
            for (int mi = 0; mi < 2; mi++) {
                uint32_t ah[4], al[4];
                uint32_t off = (uint32_t)((wm * 32 + mi * 16 + lrow) * 128 + kb);
                ldmat4(ah[0], ah[1], ah[2], ah[3], sAH + sw128(off));
                ldmat4(al[0], al[1], al[2], al[3], sAL + sw128(off));
#pragma unroll
                for (int ni = 0; ni < 4; ni++) {
                    const int g2 = ni >> 1, pt = ni & 1;
                    mma16816(acc[mi][ni], ah, bh[g2][pt], bh[g2][pt + 2]);
                    mma16816(acc[mi][ni], ah, bl[g2][pt], bl[g2][pt + 2]);
                    mma16816(acc[mi][ni], al, bh[g2][pt], bh[g2][pt + 2]);
                }
            }
        }
        __syncthreads();
    }

    const int crow = lid >> 2, ccol = (lid & 3) * 2;
#pragma unroll
    for (int mi = 0; mi < 2; mi++) {
#pragma unroll
        for (int ni = 0; ni < 4; ni++) {
            int n = n0 + wn * 32 + ni * 8 + ccol;
            if (n >= Nreal) continue;
            int m = m0 + wm * 32 + mi * 16 + crow;
            *(float2*)(C + (size_t)m * ldc + n) =
                make_float2(acc[mi][ni][0], acc[mi][ni][1]);
            *(float2*)(C + (size_t)(m + 8) * ldc + n) =
                make_float2(acc[mi][ni][2], acc[mi][ni][3]);
        }
    }
}

// ---------------------------------------------------------------------------
// Depthwise causal conv (4 taps) + bias — smem-tiled
// ---------------------------------------------------------------------------
#define CCH 64
#define CTT 64
__global__ __launch_bounds__(256) void conv_kernel(const float* __restrict__ cw,
                                                   const float* __restrict__ cb)
{
    __shared__ float s[(CTT + 3) * CCH];
    const int tid = threadIdx.x;
    const int c0 = blockIdx.x * CCH;
    const int tile = blockIdx.y;
    const int b = tile >> 7;
    const int t0 = (tile & 127) * CTT;
    const size_t row0 = (size_t)b * SEQ + t0;

    for (int e = tid; e < (CTT + 3) * CCH; e += 256) {
        int tl = e >> 6, c = e & 63;
        int t = t0 + tl - 3;
        float v = 0.f;
        if (t >= 0) v = g_xbcza[((size_t)b * SEQ + t) * IN_PROJ + c0 + c];
        s[e] = v;
    }
    __syncthreads();

    const int c = tid & 63, trow = tid >> 6;
    const int ch = c0 + c;
    const float w0 = cw[ch * 4 + 0], w1 = cw[ch * 4 + 1];
    const float w2 = cw[ch * 4 + 2], w3 = cw[ch * 4 + 3];
    const float bia = cb[ch];
#pragma unroll
    for (int j = 0; j < 16; j++) {
        int tl = trow + 4 * j;
        float acc = bia
            + w0 * s[(tl + 0) * CCH + c]
            + w1 * s[(tl + 1) * CCH + c]
            + w2 * s[(tl + 2) * CCH + c]
            + w3 * s[(tl + 3) * CCH + c];
        g_xconv[(row0 + tl) * CONV_DIM + ch] = acc;
    }
}

// ---------------------------------------------------------------------------
// states_kernel: dt/cumsum -> acum, dc; states. dyn smem ~51.7KB
// ---------------------------------------------------------------------------
#define CTS 132
#define XSS 33
#define STATES_SMEM ((64*CTS + 128*XSS + 2*CHUNK_) * 4)
__global__ __launch_bounds__(256) void states_kernel()
{
    extern __shared__ float smf[];
    float* Btm  = smf;                 // [64][132]
    float* Xs   = Btm + 64 * CTS;      // [128][33]
    float* acum = Xs + 128 * XSS;      // [128]
    float* darr = acum + CHUNK_;       // [128]

    const int tid = threadIdx.x;
    const int h = blockIdx.x, c = blockIdx.y, b = blockIdx.z;
    const size_t bt0 = (size_t)b * SEQ + (size_t)c * CHUNK_;
    const int chunk_id = (b * NC_ + c) * NV_ + h;

    if (tid < 128) {
        float a = g_xbcza[(bt0 + tid) * IN_PROJ + (CONV_DIM + D_INNER) + h];
        darr[tid] = (a > 20.f) ? a : log1pf(expf(a));
    }
    __syncthreads();
    if (tid < 32) {
        float v0 = darr[tid*4+0], v1 = darr[tid*4+1];
        float v2 = darr[tid*4+2], v3 = darr[tid*4+3];
        float s1 = v0+v1, s2 = s1+v2, s3 = s2+v3;
        float t = s3;
#pragma unroll
        for (int o = 1; o < 32; o <<= 1) {
            float u2 = __shfl_up_sync(0xffffffffu, t, o);
            if (tid >= o) t += u2;
        }
        float base = t - s3;
        acum[tid*4+0] = -(base+v0); acum[tid*4+1] = -(base+s1);
        acum[tid*4+2] = -(base+s2); acum[tid*4+3] = -(base+s3);
    }
    __syncthreads();
    const float alast = acum[127];
    if (tid < 128) {
        darr[tid] = __expf(alast - acum[tid]);
        g_acum[(size_t)chunk_id * CHUNK_ + tid] = acum[tid];
    }
    if (tid == 0) g_dc[chunk_id] = __expf(alast);

#pragma unroll
    for (int pass = 0; pass < 8; pass++) {
        int r = pass * 16 + (tid >> 4);
        int col = (tid & 15) * 4;
        float4 bv = *(const float4*)(g_xconv + (bt0 + r) * CONV_DIM
                                     + D_INNER + h*DSTATE + col);
        Btm[(col+0)*CTS + r] = bv.x; Btm[(col+1)*CTS + r] = bv.y;
        Btm[(col+2)*CTS + r] = bv.z; Btm[(col+3)*CTS + r] = bv.w;
    }
#pragma unroll
    for (int pass = 0; pass < 4; pass++) {
        int r = pass * 32 + (tid >> 3);
        int col = (tid & 7) * 4;
        float4 xv = *(const float4*)(g_xconv + (bt0 + r) * CONV_DIM + h*HEADDIM + col);
        Xs[r*XSS + col+0] = xv.x; Xs[r*XSS + col+1] = xv.y;
        Xs[r*XSS + col+2] = xv.z; Xs[r*XSS + col+3] = xv.w;
    }
    __syncthreads();

    {
        const int n  = tid >> 2;
        const int pg = tid & 3;
        float acc[8] = {};
        for (int l = 0; l < 128; l++) {
            float bv = Btm[n*CTS + l] * darr[l];
#pragma unroll
            for (int j = 0; j < 8; j++) acc[j] += bv * Xs[l*XSS + pg*8 + j];
        }
        size_t base = (size_t)chunk_id * (HEADDIM * DSTATE);
#pragma unroll
        for (int j = 0; j < 8; j++)
            g_states[base + (size_t)(pg*8 + j) * DSTATE + n] = acc[j];
    }
}

// ---------------------------------------------------------------------------
__global__ void scan_kernel()
{
    const int bh = blockIdx.x;
    const int b = bh >> 5, h = bh & 31;
    const int e = threadIdx.x * 4;
    float4 S = make_float4(0.f,0.f,0.f,0.f);
    for (int c = 0; c < NC_; c++) {
        const int cid = (b * NC_ + c) * NV_ + h;
        size_t base = (size_t)cid * (HEADDIM * DSTATE) + e;
        *(float4*)&g_prevs[base] = S;
        float4 st = *(const float4*)&g_states[base];
        float d = g_dc[cid];
        S.x = S.x*d + st.x; S.y = S.y*d + st.y;
        S.z = S.z*d + st.z; S.w = S.w*d + st.w;
    }
}

// ---------------------------------------------------------------------------
// y_kernel: G=C.B^T via HMMA split-bf16 (masked) -> Ps; Y_diag + Y_off +
// D*x + SiLU; writes split-bf16 y for out-proj. One block per (h,c,b).
// Each bf16 tile is 128 rows x 128 B = 16384 B (fixed from R10's 8192).
// ---------------------------------------------------------------------------
#define YK_F (16896 + 8320 + 4224 + 2080 + 256)
#define YK_BF_OFF (YK_F * 4)
#define YK_TILE 16384
#define YK_SMEM (YK_BF_OFF + 4 * YK_TILE)
__global__ __launch_bounds__(256) void y_kernel(
    const float* __restrict__ z_bias, const float* __restrict__ Dvec,
    __nv_bfloat16* __restrict__ yhi, __nv_bfloat16* __restrict__ ylo)
{
    extern __shared__ float smf[];
    float* Ps   = smf;                  // [128][132]
    float* Cs   = Ps + 16896;           // [128][65]
    float* Xs   = Cs + 8320;            // [128][33]
    float* Pv   = Xs + 4224;            // [32][65]
    float* acum = Pv + 2080;            // [128]
    float* ea   = acum + 128;           // [128]
    char* smb = (char*)smf;
    const uint32_t sBase = smem_u32(smb);
    const uint32_t sCH = sBase + YK_BF_OFF;
    const uint32_t sCL = sCH + YK_TILE;
    const uint32_t sBH = sCL + YK_TILE;
    const uint32_t sBL = sBH + YK_TILE;

    const int tid = threadIdx.x;
    const int wid = tid >> 5, lid = tid & 31;
    const int wm = wid & 1, wn = wid >> 1;     // 2 x 4 warps over 128x128 G
    const int h = blockIdx.x, c = blockIdx.y, b = blockIdx.z;
    const size_t bt0 = (size_t)b * SEQ + (size_t)c * CHUNK_;
    const int chunk_id = (b * NC_ + c) * NV_ + h;

    if (tid < 128) {
        float a = g_acum[(size_t)chunk_id * CHUNK_ + tid];
        acum[tid] = a;
        ea[tid] = __expf(a);
    }

    // load C (fp32 Cs + split bf16 CH/CL) and B (bf16 BH/BL)
#pragma unroll
    for (int pass = 0; pass < 8; pass++) {
        int r = pass * 16 + (tid >> 4);
        int col = (tid & 15) * 4;
        const float* row = g_xconv + (bt0 + r) * CONV_DIM;
        float4 cv = *(const float4*)(row + D_INNER + NQK*DSTATE + h*DSTATE + col);
        Cs[r*65 + col+0] = cv.x; Cs[r*65 + col+1] = cv.y;
        Cs[r*65 + col+2] = cv.z; Cs[r*65 + col+3] = cv.w;
        float a4[4] = {cv.x, cv.y, cv.z, cv.w};
        __nv_bfloat16 hh[4], ll[4];
#pragma unroll
        for (int j = 0; j < 4; j++) {
            hh[j] = __float2bfloat16(a4[j]);
            ll[j] = __float2bfloat16(a4[j] - __bfloat162float(hh[j]));
        }
        uint32_t off = sw128((uint32_t)(r * 128 + col * 2));
        *(uint2*)(smb + YK_BF_OFF + off) =
            make_uint2(*(uint32_t*)&hh[0], *(uint32_t*)&hh[2]);
        *(uint2*)(smb + YK_BF_OFF + YK_TILE + off) =
            make_uint2(*(uint32_t*)&ll[0], *(uint32_t*)&ll[2]);

        float4 bv = *(const float4*)(row + D_INNER + h*DSTATE + col);
        float b4[4] = {bv.x, bv.y, bv.z, bv.w};
#pragma unroll
        for (int j = 0; j < 4; j++) {
            hh[j] = __float2bfloat16(b4[j]);
            ll[j] = __float2bfloat16(b4[j] - __bfloat162float(hh[j]));
        }
        *(uint2*)(smb + YK_BF_OFF + 2*YK_TILE + off) =
            make_uint2(*(uint32_t*)&hh[0], *(uint32_t*)&hh[2]);
        *(uint2*)(smb + YK_BF_OFF + 3*YK_TILE + off) =
            make_uint2(*(uint32_t*)&ll[0], *(uint32_t*)&ll[2]);
    }
    // X fp32
#pragma unroll
    for (int pass = 0; pass < 4; pass++) {
        int r = pass * 32 + (tid >> 3);
        int col = (tid & 7) * 4;
        float4 xv = *(const float4*)(g_xconv + (bt0 + r) * CONV_DIM + h*HEADDIM + col);
        Xs[r*XSS + col+0] = xv.x; Xs[r*XSS + col+1] = xv.y;
        Xs[r*XSS + col+2] = xv.z; Xs[r*XSS + col+3] = xv.w;
    }
    // prev states
    size_t pbase = (size_t)chunk_id * (HEADDIM * DSTATE);
#pragma unroll
    for (int pass = 0; pass < 2; pass++) {
        int idx = pass * 256 + tid;
        int p = idx >> 4, col = (idx & 15) * 4;
        float4 v = *(const float4*)(g_prevs + pbase + (size_t)p * DSTATE + col);
        Pv[p*65 + col+0] = v.x; Pv[p*65 + col+1] = v.y;
        Pv[p*65 + col+2] = v.z; Pv[p*65 + col+3] = v.w;
    }
    __syncthreads();

    // --- G = C.B^T via HMMA (3-pass split-bf16), K=64 ---
    {
        float gacc[4][4][4];
#pragma unroll
        for (int i = 0; i < 4; i++)
#pragma unroll
            for (int j = 0; j < 4; j++)
#pragma unroll
                for (int q = 0; q < 4; q++) gacc[i][j][q] = 0.f;

        const int lrow = lid & 15;
        const int lkb  = (lid >> 4) * 16;
#pragma unroll
        for (int ks = 0; ks < 4; ks++) {
            const int kb = ks * 32 + lkb;
            uint32_t bh[2][4], bl[2][4];
#pragma unroll
            for (int g2 = 0; g2 < 2; g2++) {
                uint32_t off = (uint32_t)((wn * 32 + g2 * 16 + lrow) * 128 + kb);
                ldmat4(bh[g2][0], bh[g2][1], bh[g2][2], bh[g2][3], sBH + sw128(off));
                ldmat4(bl[g2][0], bl[g2][1], bl[g2][2], bl[g2][3], sBL + sw128(off));
            }
#pragma unroll
            for (int mi = 0; mi < 4; mi++) {
                uint32_t ah[4], al4[4];
                uint32_t off = (uint32_t)((wm * 64 + mi * 16 + lrow) * 128 + kb);
                ldmat4(ah[0], ah[1], ah[2], ah[3], sCH + sw128(off));
                ldmat4(al4[0], al4[1], al4[2], al4[3], sCL + sw128(off));
#pragma unroll
                for (int ni = 0; ni < 4; ni++) {
                    const int g2 = ni >> 1, pt = ni & 1;
                    mma16816(gacc[mi][ni], ah, bh[g2][pt], bh[g2][pt + 2]);
                    mma16816(gacc[mi][ni], ah, bl[g2][pt], bl[g2][pt + 2]);
                    mma16816(gacc[mi][ni], al4, bh[g2][pt], bh[g2][pt + 2]);
                }
            }
        }

        // mask + store to Ps
        const int crow = lid >> 2, ccol = (lid & 3) * 2;
        float alr[8], asc[8];
#pragma unroll
        for (int mi = 0; mi < 4; mi++) {
            alr[mi*2]   = acum[wm*64 + mi*16 + crow];
            alr[mi*2+1] = acum[wm*64 + mi*16 + crow + 8];
        }
#pragma unroll
        for (int ni = 0; ni < 4; ni++) {
            asc[ni*2]   = acum[wn*32 + ni*8 + ccol];
            asc[ni*2+1] = acum[wn*32 + ni*8 + ccol + 1];
        }
#pragma unroll
        for (int mi = 0; mi < 4; mi++) {
#pragma unroll
            for (int ni = 0; ni < 4; ni++) {
                int l0 = wm*64 + mi*16 + crow;
                int s0q = wn*32 + ni*8 + ccol;
                float v00 = (s0q   <= l0)   ? gacc[mi][ni][0] * __expf(alr[mi*2]   - asc[ni*2])   : 0.f;
                float v01 = (s0q+1 <= l0)   ? gacc[mi][ni][1] * __expf(alr[mi*2]   - asc[ni*2+1]) : 0.f;
                float v10 = (s0q   <= l0+8) ? gacc[mi][ni][2] * __expf(alr[mi*2+1] - asc[ni*2])   : 0.f;
                float v11 = (s0q+1 <= l0+8) ? gacc[mi][ni][3] * __expf(alr[mi*2+1] - asc[ni*2+1]) : 0.f;
                *(float2*)&Ps[l0*CTS + s0q]       = make_float2(v00, v01);
                *(float2*)&Ps[(l0+8)*CTS + s0q]   = make_float2(v10, v11);
            }
        }
    }
    __syncthreads();

    // --- Y_diag = Ps @ X ; Y_off = ea * Cs @ Pv^T ; combine + gate ---
    {
        const int lq = tid >> 3, pq = tid & 7;
        float yd[4][4] = {};
        for (int s = 0; s < 128; s++) {
            float bf0 = Xs[s*XSS + pq*4+0];
            float bf1 = Xs[s*XSS + pq*4+1];
            float bf2 = Xs[s*XSS + pq*4+2];
            float bf3 = Xs[s*XSS + pq*4+3];
#pragma unroll
            for (int i = 0; i < 4; i++) {
                float a = Ps[(lq*4+i)*CTS + s];
                yd[i][0] += a*bf0; yd[i][1] += a*bf1;
                yd[i][2] += a*bf2; yd[i][3] += a*bf3;
            }
        }
        float yo[4][4] = {};
        for (int n = 0; n < 64; n++) {
            float p0v = Pv[(pq*4+0)*65 + n];
            float p1v = Pv[(pq*4+1)*65 + n];
            float p2v = Pv[(pq*4+2)*65 + n];
            float p3v = Pv[(pq*4+3)*65 + n];
#pragma unroll
            for (int i = 0; i < 4; i++) {
                float cvv = Cs[(lq*4+i)*65 + n];
                yo[i][0] += cvv*p0v; yo[i][1] += cvv*p1v;
                yo[i][2] += cvv*p2v; yo[i][3] += cvv*p3v;
            }
        }
        const float Dh = Dvec[h];
        const int ch0 = h * HEADDIM + pq * 4;
#pragma unroll
        for (int i = 0; i < 4; i++) {
            int l = lq*4 + i;
            float e = ea[l];
            float4 z4 = *(const float4*)(g_xbcza + (bt0 + l) * IN_PROJ
                                         + CONV_DIM + ch0);
            float zb0 = z_bias[ch0+0], zb1 = z_bias[ch0+1];
            float zb2 = z_bias[ch0+2], zb3 = z_bias[ch0+3];
            float yv[4];
            yv[0] = yd[i][0] + e*yo[i][0] + Dh * Xs[l*XSS + pq*4+0];
            yv[1] = yd[i][1] + e*yo[i][1] + Dh * Xs[l*XSS + pq*4+1];
            yv[2] = yd[i][2] + e*yo[i][2] + Dh * Xs[l*XSS + pq*4+2];
            yv[3] = yd[i][3] + e*yo[i][3] + Dh * Xs[l*XSS + pq*4+3];
            float zz[4] = {z4.x+zb0, z4.y+zb1, z4.z+zb2, z4.w+zb3};
            __nv_bfloat16 hb[4], lb[4];
#pragma unroll
            for (int j = 0; j < 4; j++) {
                float sg = zz[j] / (1.f + __expf(-zz[j]));
                float v = yv[j] * sg;
                hb[j] = __float2bfloat16(v);
                lb[j] = __float2bfloat16(v - __bfloat162float(hb[j]));
            }
            size_t o = (bt0 + l) * (size_t)D_INNER + ch0;
            *(uint2*)(yhi + o) = make_uint2(*(uint32_t*)&hb[0], *(uint32_t*)&hb[2]);
            *(uint2*)(ylo + o) = make_uint2(*(uint32_t*)&lb[0], *(uint32_t*)&lb[2]);
        }
    }
}

// ---------------------------------------------------------------------------
extern "C" void kernel_launch(void* const* d_in, const int* in_sizes, int n_in,
                              void* d_out, int out_size)
{
    const float* u      = (const float*)d_in[0];
    const float* W_in   = (const float*)d_in[1];
    const float* conv_w = (const float*)d_in[2];
    const float* conv_b = (const float*)d_in[3];
    const float* z_bias = (const float*)d_in[4];
    const float* Dvec   = (const float*)d_in[5];
    const float* W_out  = (const float*)d_in[6];
    float* out = (float*)d_out;

    float *p_xbcza = nullptr;
    __nv_bfloat16 *p_ah, *p_al, *p_w1h, *p_w1l, *p_w2h, *p_w2l;
    cudaGetSymbolAddress((void**)&p_xbcza, g_xbcza);
    cudaGetSymbolAddress((void**)&p_ah, g_act_hi);
    cudaGetSymbolAddress((void**)&p_al, g_act_lo);
    cudaGetSymbolAddress((void**)&p_w1h, g_w1_hi);
    cudaGetSymbolAddress((void**)&p_w1l, g_w1_lo);
    cudaGetSymbolAddress((void**)&p_w2h, g_w2_hi);
    cudaGetSymbolAddress((void**)&p_w2l, g_w2_lo);

    static int attr_set = 0;
    if (!attr_set) {
        cudaFuncSetAttribute(gemm_hmma,
            cudaFuncAttributeMaxDynamicSharedMemorySize, GEMM_SMEM);
        cudaFuncSetAttribute(states_kernel,
            cudaFuncAttributeMaxDynamicSharedMemorySize, STATES_SMEM);
        cudaFuncSetAttribute(y_kernel,
            cudaFuncAttributeMaxDynamicSharedMemorySize, YK_SMEM);
        attr_set = 1;
    }

    // split conversions
    cvt_split<<<(BT*1024)/1024, 256>>>(u, p_ah, p_al, BT*1024, BT*1024);
    cvt_split<<<(IN_PROJ_PAD*1024)/1024, 256>>>(W_in, p_w1h, p_w1l,
                                                IN_PROJ*1024, IN_PROJ_PAD*1024);
    cvt_split<<<(1024*1024)/1024, 256>>>(W_out, p_w2h, p_w2l, 1024*1024, 1024*1024);

    // in-proj
    {
        dim3 grid(IN_PROJ_PAD / 128, BT / 128);
        gemm_hmma<<<grid, 512, GEMM_SMEM>>>(p_ah, p_al, p_w1h, p_w1l,
                                            p_xbcza, D_MODEL, IN_PROJ, IN_PROJ);
    }
    // conv
    {
        dim3 grid(CONV_DIM / CCH, BT / CTT);
        conv_kernel<<<grid, 256>>>(conv_w, conv_b);
    }
    // states
    {
        dim3 grid(NV_, NC_, BATCH);
        states_kernel<<<grid, 256, STATES_SMEM>>>();
    }
    scan_kernel<<<BATCH * NV_, 512>>>();
    // Y (G-HMMA + Y_diag + Y_off + gating + split-bf16 output)
    {
        dim3 grid(NV_, NC_, BATCH);
        y_kernel<<<grid, 256, YK_SMEM>>>(z_bias, Dvec, p_ah, p_al);
    }
    // out-proj (consumes y_kernel's split output)
    {
        dim3 grid(D_MODEL / 128, BT / 128);
        gemm_hmma<<<grid, 512, GEMM_SMEM>>>(p_ah, p_al, p_w2h, p_w2l,
                                            out, D_INNER, D_MODEL, D_MODEL);
    }
}

// round 12
// speedup vs baseline: 1.4662x; 1.4662x over previous
#include <cuda_runtime.h>
#include <cuda_bf16.h>
#include <cstdint>
#include <cstddef>

#define D_MODEL   1024
#define D_INNER   1024
#define NQK       32
#define NV_       32
#define DSTATE    64
#define DCONV     4
#define CHUNK_    128
#define CONV_DIM  5120
#define HEADDIM   32
#define IN_PROJ   6176
#define IN_PROJ_PAD 6272
#define BATCH     2
#define SEQ       8192
#define BT        16384
#define NC_       64

// ---- scratch (device globals) ----
__device__ __align__(16) float g_xbcza[(size_t)BT * IN_PROJ];
__device__ __align__(16) float g_xconv[(size_t)BT * CONV_DIM];
__device__ __align__(16) float g_y[(size_t)BT * D_INNER];
__device__ __align__(16) float g_states[(size_t)BATCH * NC_ * NV_ * HEADDIM * DSTATE];
__device__ __align__(16) float g_prevs [(size_t)BATCH * NC_ * NV_ * HEADDIM * DSTATE];
__device__ __align__(16) float g_acum  [(size_t)BATCH * NC_ * NV_ * CHUNK_];
__device__ __align__(16) float g_dc    [BATCH * NC_ * NV_];
__device__ __align__(16) __nv_bfloat16 g_act_hi[(size_t)BT * 1024];
__device__ __align__(16) __nv_bfloat16 g_act_lo[(size_t)BT * 1024];
__device__ __align__(16) __nv_bfloat16 g_w1_hi [(size_t)IN_PROJ_PAD * 1024];
__device__ __align__(16) __nv_bfloat16 g_w1_lo [(size_t)IN_PROJ_PAD * 1024];
__device__ __align__(16) __nv_bfloat16 g_w2_hi [(size_t)1024 * 1024];
__device__ __align__(16) __nv_bfloat16 g_w2_lo [(size_t)1024 * 1024];

// ===========================================================================
// split-bf16 conversion
// ===========================================================================
__global__ void cvt_split(const float* __restrict__ s,
                          __nv_bfloat16* __restrict__ hi,
                          __nv_bfloat16* __restrict__ lo,
                          int n_real, int n_total)
{
    int i = (blockIdx.x * 256 + threadIdx.x) * 4;
    if (i >= n_total) return;
    __nv_bfloat16 h[4], l[4];
    if (i < n_real) {
        float4 v = *(const float4*)(s + i);
        float a[4] = {v.x, v.y, v.z, v.w};
#pragma unroll
        for (int j = 0; j < 4; j++) {
            h[j] = __float2bfloat16(a[j]);
            l[j] = __float2bfloat16(a[j] - __bfloat162float(h[j]));
        }
    } else {
#pragma unroll
        for (int j = 0; j < 4; j++) { h[j] = __float2bfloat16(0.f); l[j] = h[j]; }
    }
    *(__nv_bfloat162*)(hi + i)     = __nv_bfloat162(h[0], h[1]);
    *(__nv_bfloat162*)(hi + i + 2) = __nv_bfloat162(h[2], h[3]);
    *(__nv_bfloat162*)(lo + i)     = __nv_bfloat162(l[0], l[1]);
    *(__nv_bfloat162*)(lo + i + 2) = __nv_bfloat162(l[2], l[3]);
}

// ===========================================================================
// shared helpers
// ===========================================================================
__device__ __forceinline__ uint32_t smem_u32(const void* p) {
    uint32_t a;
    asm("{ .reg .u64 t; cvta.to.shared.u64 t, %1; cvt.u32.u64 %0, t; }"
        : "=r"(a) : "l"(p));
    return a;
}
__device__ __forceinline__ uint32_t sw128(uint32_t off) {
    return off ^ ((off >> 3) & 0x70);
}
__device__ __forceinline__ void ldmat4(uint32_t& r0, uint32_t& r1,
                                       uint32_t& r2, uint32_t& r3, uint32_t a) {
    asm volatile("ldmatrix.sync.aligned.m8n8.x4.shared.b16 {%0,%1,%2,%3}, [%4];"
                 : "=r"(r0), "=r"(r1), "=r"(r2), "=r"(r3) : "r"(a));
}
__device__ __forceinline__ void mma16816(float* c, const uint32_t* a,
                                         uint32_t b0, uint32_t b1) {
    asm volatile(
        "mma.sync.aligned.m16n8k16.row.col.f32.bf16.bf16.f32 "
        "{%0,%1,%2,%3}, {%4,%5,%6,%7}, {%8,%9}, {%0,%1,%2,%3};"
        : "+f"(c[0]), "+f"(c[1]), "+f"(c[2]), "+f"(c[3])
        : "r"(a[0]), "r"(a[1]), "r"(a[2]), "r"(a[3]), "r"(b0), "r"(b1));
}
__device__ __forceinline__ void cp16(uint32_t dst, const void* src) {
    asm volatile("cp.async.cg.shared.global [%0], [%1], 16;"
                 :: "r"(dst), "l"(src));
}

// ===========================================================================
// HMMA split-bf16 GEMM (NT), cp.async 3-stage pipeline, 512 threads
// ===========================================================================
__device__ __forceinline__ void load_tile_async512(
    const __nv_bfloat16* __restrict__ g, int row0, int K, int k0,
    uint32_t sbase, int tid)
{
#pragma unroll
    for (int j = 0; j < 2; j++) {
        int u = tid + 512 * j;
        int row = u >> 3, cg = u & 7;
        uint32_t off = (uint32_t)(row * 128 + cg * 16);
        cp16(sbase + sw128(off), g + (size_t)(row0 + row) * K + k0 + cg * 8);
    }
}
__device__ __forceinline__ void load_stage(
    const __nv_bfloat16* Ahi, const __nv_bfloat16* Alo,
    const __nv_bfloat16* Bhi, const __nv_bfloat16* Blo,
    int m0, int n0, int K, int k0, uint32_t base, int tid)
{
    load_tile_async512(Ahi, m0, K, k0, base,         tid);
    load_tile_async512(Alo, m0, K, k0, base + 16384, tid);
    load_tile_async512(Bhi, n0, K, k0, base + 32768, tid);
    load_tile_async512(Blo, n0, K, k0, base + 49152, tid);
    asm volatile("cp.async.commit_group;");
}

#define STAGE_SZ 65536u
#define GEMM_SMEM (3 * 65536)
__global__ __launch_bounds__(512, 1)
void gemm_hmma(const __nv_bfloat16* __restrict__ Ahi,
               const __nv_bfloat16* __restrict__ Alo,
               const __nv_bfloat16* __restrict__ Bhi,
               const __nv_bfloat16* __restrict__ Blo,
               float* __restrict__ C, int K, int Nreal, int ldc)
{
    extern __shared__ char sm[];
    const uint32_t s0 = smem_u32(sm);
    const int tid = threadIdx.x;
    const int wid = tid >> 5, lid = tid & 31;
    const int wm = wid & 3, wn = wid >> 2;
    const int m0 = blockIdx.y * 128, n0 = blockIdx.x * 128;

    float acc[2][4][4];
#pragma unroll
    for (int i = 0; i < 2; i++)
#pragma unroll
        for (int j = 0; j < 4; j++)
#pragma unroll
            for (int q = 0; q < 4; q++) acc[i][j][q] = 0.f;

    const int lrow = lid & 15;
    const int lkb  = (lid >> 4) * 16;
    const int NKC = K >> 6;

    // prologue: stages 0,1 <- chunks 0,1
    load_stage(Ahi, Alo, Bhi, Blo, m0, n0, K, 0,  s0,            tid);
    load_stage(Ahi, Alo, Bhi, Blo, m0, n0, K, 64, s0 + STAGE_SZ, tid);

    int stage = 0;
    for (int kc = 0; kc < NKC; kc++) {
        if (kc + 2 < NKC) {
            int ls = stage + 2; if (ls >= 3) ls -= 3;
            load_stage(Ahi, Alo, Bhi, Blo, m0, n0, K, (kc + 2) << 6,
                       s0 + (uint32_t)ls * STAGE_SZ, tid);
            asm volatile("cp.async.wait_group 2;");
        } else if (kc + 1 < NKC) {
            asm volatile("cp.async.wait_group 1;");
        } else {
            asm volatile("cp.async.wait_group 0;");
        }
        __syncthreads();

        const uint32_t sAH = s0 + (uint32_t)stage * STAGE_SZ;
        const uint32_t sAL = sAH + 16384;
        const uint32_t sBH = sAH + 32768;
        const uint32_t sBL = sAH + 49152;
#pragma unroll
        for (int ks = 0; ks < 4; ks++) {
            const int kb = ks * 32 + lkb;
            uint32_t bh[2][4], bl[2][4];
#pragma unroll
            for (int g2 = 0; g2 < 2; g2++) {
                uint32_t off = (uint32_t)((wn * 32 + g2 * 16 + lrow) * 128 + kb);
                ldmat4(bh[g2][0], bh[g2][1], bh[g2][2], bh[g2][3], sBH + sw128(off));
                ldmat4(bl[g2][0], bl[g2][1], bl[g2][2], bl[g2][3], sBL + sw128(off));
            }
#pragma unroll
            for (int mi = 0; mi < 2; mi++) {
                uint32_t ah[4], al[4];
                uint32_t off = (uint32_t)((wm * 32 + mi * 16 + lrow) * 128 + kb);
                ldmat4(ah[0], ah[1], ah[2], ah[3], sAH + sw128(off));
                ldmat4(al[0], al[1], al[2], al[3], sAL + sw128(off));
#pragma unroll
                for (int ni = 0; ni < 4; ni++) {
                    const int g2 = ni >> 1, pt = ni & 1;
                    mma16816(acc[mi][ni], ah, bh[g2][pt], bh[g2][pt + 2]);
                    mma16816(acc[mi][ni], ah, bl[g2][pt], bl[g2][pt + 2]);
                    mma16816(acc[mi][ni], al, bh[g2][pt], bh[g2][pt + 2]);
                }
            }
        }
        __syncthreads();
        if (++stage == 3) stage = 0;
    }

    const int crow = lid >> 2, ccol = (lid & 3) * 2;
#pragma unroll
    for (int mi = 0; mi < 2; mi++) {
#pragma unroll
        for (int ni = 0; ni < 4; ni++) {
            int n = n0 + wn * 32 + ni * 8 + ccol;
            if (n >= Nreal) continue;
            int m = m0 + wm * 32 + mi * 16 + crow;
            *(float2*)(C + (size_t)m * ldc + n) =
                make_float2(acc[mi][ni][0], acc[mi][ni][1]);
            *(float2*)(C + (size_t)(m + 8) * ldc + n) =
                make_float2(acc[mi][ni][2], acc[mi][ni][3]);
        }
    }
}

// ---------------------------------------------------------------------------
// Depthwise causal conv (4 taps) + bias — smem-tiled
// ---------------------------------------------------------------------------
#define CCH 64
#define CTT 64
__global__ __launch_bounds__(256) void conv_kernel(const float* __restrict__ cw,
                                                   const float* __restrict__ cb)
{
    __shared__ float s[(CTT + 3) * CCH];
    const int tid = threadIdx.x;
    const int c0 = blockIdx.x * CCH;
    const int tile = blockIdx.y;
    const int b = tile >> 7;
    const int t0 = (tile & 127) * CTT;
    const size_t row0 = (size_t)b * SEQ + t0;

    for (int e = tid; e < (CTT + 3) * CCH; e += 256) {
        int tl = e >> 6, c = e & 63;
        int t = t0 + tl - 3;
        float v = 0.f;
        if (t >= 0) v = g_xbcza[((size_t)b * SEQ + t) * IN_PROJ + c0 + c];
        s[e] = v;
    }
    __syncthreads();

    const int c = tid & 63, trow = tid >> 6;
    const int ch = c0 + c;
    const float w0 = cw[ch * 4 + 0], w1 = cw[ch * 4 + 1];
    const float w2 = cw[ch * 4 + 2], w3 = cw[ch * 4 + 3];
    const float bia = cb[ch];
#pragma unroll
    for (int j = 0; j < 16; j++) {
        int tl = trow + 4 * j;
        float acc = bia
            + w0 * s[(tl + 0) * CCH + c]
            + w1 * s[(tl + 1) * CCH + c]
            + w2 * s[(tl + 2) * CCH + c]
            + w3 * s[(tl + 3) * CCH + c];
        g_xconv[(row0 + tl) * CONV_DIM + ch] = acc;
    }
}

// ---------------------------------------------------------------------------
// Chunk kernel (R9 scalar version): per (h, c, b). dyn smem 153,088 B.
// ---------------------------------------------------------------------------
#define CTS 132
#define XSS 33
__global__ __launch_bounds__(256, 1) void chunk_kernel()
{
    extern __shared__ float smf[];
    float* Ct   = smf;
    float* Btm  = Ct + 64 * CTS;
    float* Xs   = Btm + 64 * CTS;
    float* Ps   = Xs + 128 * XSS;
    float* acum = Ps + 128 * CTS;
    float* darr = acum + CHUNK_;

    const int tid = threadIdx.x;
    const int h = blockIdx.x, c = blockIdx.y, b = blockIdx.z;
    const size_t bt0 = (size_t)b * SEQ + (size_t)c * CHUNK_;
    const int chunk_id = (b * NC_ + c) * NV_ + h;

    if (tid < 128) {
        float a = g_xbcza[(bt0 + tid) * IN_PROJ + (CONV_DIM + D_INNER) + h];
        darr[tid] = (a > 20.f) ? a : log1pf(expf(a));
    }
    __syncthreads();
    if (tid < 32) {
        float v0 = darr[tid*4+0], v1 = darr[tid*4+1];
        float v2 = darr[tid*4+2], v3 = darr[tid*4+3];
        float s1 = v0+v1, s2 = s1+v2, s3 = s2+v3;
        float t = s3;
#pragma unroll
        for (int o = 1; o < 32; o <<= 1) {
            float u2 = __shfl_up_sync(0xffffffffu, t, o);
            if (tid >= o) t += u2;
        }
        float base = t - s3;
        acum[tid*4+0] = -(base+v0); acum[tid*4+1] = -(base+s1);
        acum[tid*4+2] = -(base+s2); acum[tid*4+3] = -(base+s3);
    }
    __syncthreads();
    const float alast = acum[127];
    if (tid < 128) {
        darr[tid] = __expf(alast - acum[tid]);
        g_acum[(size_t)chunk_id * CHUNK_ + tid] = acum[tid];
    }
    if (tid == 0) g_dc[chunk_id] = __expf(alast);

#pragma unroll
    for (int pass = 0; pass < 8; pass++) {
        int r = pass * 16 + (tid >> 4);
        int col = (tid & 15) * 4;
        const float* row = g_xconv + (bt0 + r) * CONV_DIM;
        float4 cv = *(const float4*)(row + D_INNER + NQK*DSTATE + h*DSTATE + col);
        Ct[(col+0)*CTS + r] = cv.x; Ct[(col+1)*CTS + r] = cv.y;
        Ct[(col+2)*CTS + r] = cv.z; Ct[(col+3)*CTS + r] = cv.w;
        float4 bv = *(const float4*)(row + D_INNER + h*DSTATE + col);
        Btm[(col+0)*CTS + r] = bv.x; Btm[(col+1)*CTS + r] = bv.y;
        Btm[(col+2)*CTS + r] = bv.z; Btm[(col+3)*CTS + r] = bv.w;
    }
#pragma unroll
    for (int pass = 0; pass < 4; pass++) {
        int r = pass * 32 + (tid >> 3);
        int col = (tid & 7) * 4;
        float4 xv = *(const float4*)(g_xconv + (bt0 + r) * CONV_DIM + h*HEADDIM + col);
        Xs[r*XSS + col+0] = xv.x; Xs[r*XSS + col+1] = xv.y;
        Xs[r*XSS + col+2] = xv.z; Xs[r*XSS + col+3] = xv.w;
    }
    __syncthreads();

    const int ty = tid >> 4, tx = tid & 15;
    float accG[8][8];
#pragma unroll
    for (int i = 0; i < 8; i++)
#pragma unroll
        for (int j = 0; j < 8; j++) accG[i][j] = 0.f;
#pragma unroll 4
    for (int n = 0; n < 64; n++) {
        float4 a0 = *(const float4*)&Ct[n*CTS + ty*8];
        float4 a1 = *(const float4*)&Ct[n*CTS + ty*8 + 4];
        float4 b0 = *(const float4*)&Btm[n*CTS + tx*8];
        float4 b1 = *(const float4*)&Btm[n*CTS + tx*8 + 4];
        float av[8] = {a0.x,a0.y,a0.z,a0.w,a1.x,a1.y,a1.z,a1.w};
        float bv[8] = {b0.x,b0.y,b0.z,b0.w,b1.x,b1.y,b1.z,b1.w};
#pragma unroll
        for (int i = 0; i < 8; i++)
#pragma unroll
            for (int j = 0; j < 8; j++) accG[i][j] += av[i] * bv[j];
    }
    float al[8], asv[8];
#pragma unroll
    for (int i = 0; i < 8; i++) al[i] = acum[ty*8 + i];
#pragma unroll
    for (int j = 0; j < 8; j++) asv[j] = acum[tx*8 + j];
#pragma unroll
    for (int i = 0; i < 8; i++) {
        int l = ty*8 + i;
#pragma unroll
        for (int j = 0; j < 8; j++) {
            int s = tx*8 + j;
            accG[i][j] = (s <= l) ? accG[i][j] * __expf(al[i] - asv[j]) : 0.f;
        }
        *(float4*)&Ps[l*CTS + tx*8]     = make_float4(accG[i][0],accG[i][1],accG[i][2],accG[i][3]);
        *(float4*)&Ps[l*CTS + tx*8 + 4] = make_float4(accG[i][4],accG[i][5],accG[i][6],accG[i][7]);
    }
    __syncthreads();

    {
        const int lq = tid >> 3, pq = tid & 7;
        float acc[4][4] = {};
        for (int s = 0; s < 128; s++) {
            float bf0 = Xs[s*XSS + pq*4+0];
            float bf1 = Xs[s*XSS + pq*4+1];
            float bf2 = Xs[s*XSS + pq*4+2];
            float bf3 = Xs[s*XSS + pq*4+3];
#pragma unroll
            for (int i = 0; i < 4; i++) {
                float a = Ps[(lq*4+i)*CTS + s];
                acc[i][0] += a*bf0; acc[i][1] += a*bf1;
                acc[i][2] += a*bf2; acc[i][3] += a*bf3;
            }
        }
#pragma unroll
        for (int i = 0; i < 4; i++) {
            size_t row = (bt0 + lq*4 + i) * D_INNER + h*HEADDIM + pq*4;
            *(float4*)&g_y[row] = make_float4(acc[i][0],acc[i][1],acc[i][2],acc[i][3]);
        }
    }

    {
        const int n  = tid >> 2;
        const int pg = tid & 3;
        float acc[8] = {};
        for (int l = 0; l < 128; l++) {
            float bv = Btm[n*CTS + l] * darr[l];
#pragma unroll
            for (int j = 0; j < 8; j++) acc[j] += bv * Xs[l*XSS + pg*8 + j];
        }
        size_t base = (size_t)chunk_id * (HEADDIM * DSTATE);
#pragma unroll
        for (int j = 0; j < 8; j++)
            g_states[base + (size_t)(pg*8 + j) * DSTATE + n] = acc[j];
    }
}

// ---------------------------------------------------------------------------
__global__ void scan_kernel()
{
    const int bh = blockIdx.x;
    const int b = bh >> 5, h = bh & 31;
    const int e = threadIdx.x * 4;
    float4 S = make_float4(0.f,0.f,0.f,0.f);
    for (int c = 0; c < NC_; c++) {
        const int cid = (b * NC_ + c) * NV_ + h;
        size_t base = (size_t)cid * (HEADDIM * DSTATE) + e;
        *(float4*)&g_prevs[base] = S;
        float4 st = *(const float4*)&g_states[base];
        float d = g_dc[cid];
        S.x = S.x*d + st.x; S.y = S.y*d + st.y;
        S.z = S.z*d + st.z; S.w = S.w*d + st.w;
    }
}

// ---------------------------------------------------------------------------
// Y_off + D*x + SiLU gating (R9 scalar version).
// ---------------------------------------------------------------------------
__global__ __launch_bounds__(256) void yoff_kernel(
    const float* __restrict__ z_bias, const float* __restrict__ Dvec)
{
    __shared__ float Cs[128 * 65];
    __shared__ float Pv[32 * 65];
    __shared__ float ea[128];
    const int tid = threadIdx.x;
    const int h = blockIdx.x, c = blockIdx.y, b = blockIdx.z;
    const size_t bt0 = (size_t)b * SEQ + (size_t)c * CHUNK_;
    const int chunk_id = (b * NC_ + c) * NV_ + h;

    if (tid < 128) ea[tid] = __expf(g_acum[(size_t)chunk_id * CHUNK_ + tid]);
#pragma unroll
    for (int pass = 0; pass < 8; pass++) {
        int idx = pass * 256 + tid;
        int r = idx >> 4, col = (idx & 15) * 4;
        float4 v = *(const float4*)(g_xconv + (bt0 + r) * CONV_DIM
                                    + D_INNER + NQK*DSTATE + h*DSTATE + col);
        Cs[r*65 + col+0] = v.x; Cs[r*65 + col+1] = v.y;
        Cs[r*65 + col+2] = v.z; Cs[r*65 + col+3] = v.w;
    }
    size_t pbase = (size_t)chunk_id * (HEADDIM * DSTATE);
#pragma unroll
    for (int pass = 0; pass < 2; pass++) {
        int idx = pass * 256 + tid;
        int p = idx >> 4, col = (idx & 15) * 4;
        float4 v = *(const float4*)(g_prevs + pbase + (size_t)p * DSTATE + col);
        Pv[p*65 + col+0] = v.x; Pv[p*65 + col+1] = v.y;
        Pv[p*65 + col+2] = v.z; Pv[p*65 + col+3] = v.w;
    }
    __syncthreads();

    const int l = tid >> 1;
    const int p0 = (tid & 1) * 16;
    const float e = ea[l];
    float acc[16];
#pragma unroll
    for (int j = 0; j < 16; j++) acc[j] = 0.f;
    for (int n = 0; n < 64; n++) {
        float cv = Cs[l*65 + n];
#pragma unroll
        for (int j = 0; j < 16; j++) acc[j] += cv * Pv[(p0+j)*65 + n];
    }
    const float Dh = Dvec[h];
#pragma unroll
    for (int j = 0; j < 16; j++) {
        int p = p0 + j;
        int ch = h * HEADDIM + p;
        size_t oidx = (bt0 + l) * D_INNER + ch;
        float x  = g_xconv[(bt0 + l) * CONV_DIM + ch];
        float zd = g_xbcza[(bt0 + l) * IN_PROJ + CONV_DIM + ch] + z_bias[ch];
        float sg = zd / (1.f + __expf(-zd));
        g_y[oidx] = (g_y[oidx] + e * acc[j] + Dh * x) * sg;
    }
}

// ---------------------------------------------------------------------------
extern "C" void kernel_launch(void* const* d_in, const int* in_sizes, int n_in,
                              void* d_out, int out_size)
{
    const float* u      = (const float*)d_in[0];
    const float* W_in   = (const float*)d_in[1];
    const float* conv_w = (const float*)d_in[2];
    const float* conv_b = (const float*)d_in[3];
    const float* z_bias = (const float*)d_in[4];
    const float* Dvec   = (const float*)d_in[5];
    const float* W_out  = (const float*)d_in[6];
    float* out = (float*)d_out;

    float *p_xbcza = nullptr, *p_y = nullptr;
    __nv_bfloat16 *p_ah, *p_al, *p_w1h, *p_w1l, *p_w2h, *p_w2l;
    cudaGetSymbolAddress((void**)&p_xbcza, g_xbcza);
    cudaGetSymbolAddress((void**)&p_y, g_y);
    cudaGetSymbolAddress((void**)&p_ah, g_act_hi);
    cudaGetSymbolAddress((void**)&p_al, g_act_lo);
    cudaGetSymbolAddress((void**)&p_w1h, g_w1_hi);
    cudaGetSymbolAddress((void**)&p_w1l, g_w1_lo);
    cudaGetSymbolAddress((void**)&p_w2h, g_w2_hi);
    cudaGetSymbolAddress((void**)&p_w2l, g_w2_lo);

    static int attr_set = 0;
    if (!attr_set) {
        cudaFuncSetAttribute(gemm_hmma,
            cudaFuncAttributeMaxDynamicSharedMemorySize, GEMM_SMEM);
        size_t csm = (64*CTS + 64*CTS + 128*XSS + 128*CTS + 2*CHUNK_) * sizeof(float);
        cudaFuncSetAttribute(chunk_kernel,
            cudaFuncAttributeMaxDynamicSharedMemorySize, (int)csm);
        attr_set = 1;
    }

    // split conversions
    cvt_split<<<(BT*1024)/1024, 256>>>(u, p_ah, p_al, BT*1024, BT*1024);
    cvt_split<<<(IN_PROJ_PAD*1024)/1024, 256>>>(W_in, p_w1h, p_w1l,
                                                IN_PROJ*1024, IN_PROJ_PAD*1024);
    cvt_split<<<(1024*1024)/1024, 256>>>(W_out, p_w2h, p_w2l, 1024*1024, 1024*1024);

    // in-proj
    {
        dim3 grid(IN_PROJ_PAD / 128, BT / 128);
        gemm_hmma<<<grid, 512, GEMM_SMEM>>>(p_ah, p_al, p_w1h, p_w1l,
                                            p_xbcza, D_MODEL, IN_PROJ, IN_PROJ);
    }
    // conv
    {
        dim3 grid(CONV_DIM / CCH, BT / CTT);
        conv_kernel<<<grid, 256>>>(conv_w, conv_b);
    }
    // chunk
    {
        size_t csm = (64*CTS + 64*CTS + 128*XSS + 128*CTS + 2*CHUNK_) * sizeof(float);
        dim3 grid(NV_, NC_, BATCH);
        chunk_kernel<<<grid, 256, csm>>>();
    }
    scan_kernel<<<BATCH * NV_, 512>>>();
    {
        dim3 grid(NV_, NC_, BATCH);
        yoff_kernel<<<grid, 256>>>(z_bias, Dvec);
    }
    // out-proj
    cvt_split<<<(BT*1024)/1024, 256>>>(p_y, p_ah, p_al, BT*1024, BT*1024);
    {
        dim3 grid(D_MODEL / 128, BT / 128);
        gemm_hmma<<<grid, 512, GEMM_SMEM>>>(p_ah, p_al, p_w2h, p_w2l,
                                            out, D_INNER, D_MODEL, D_MODEL);
    }
}

// round 13
// speedup vs baseline: 1.5301x; 1.0435x over previous
#include <cuda_runtime.h>
#include <cuda_bf16.h>
#include <cstdint>
#include <cstddef>

#define D_MODEL   1024
#define D_INNER   1024
#define NQK       32
#define NV_       32
#define DSTATE    64
#define DCONV     4
#define CHUNK_    128
#define CONV_DIM  5120
#define HEADDIM   32
#define IN_PROJ   6176
#define IN_PROJ_PAD 6272
#define BATCH     2
#define SEQ       8192
#define BT        16384
#define NC_       64

// ---- scratch (device globals) ----
__device__ __align__(16) float g_xbcza[(size_t)BT * IN_PROJ];
__device__ __align__(16) float g_y[(size_t)BT * D_INNER];
__device__ __align__(16) float g_states[(size_t)BATCH * NC_ * NV_ * HEADDIM * DSTATE];
__device__ __align__(16) float g_prevs [(size_t)BATCH * NC_ * NV_ * HEADDIM * DSTATE];
__device__ __align__(16) float g_acum  [(size_t)BATCH * NC_ * NV_ * CHUNK_];
__device__ __align__(16) float g_dc    [BATCH * NC_ * NV_];
__device__ __align__(16) __nv_bfloat16 g_act_hi[(size_t)BT * 1024];
__device__ __align__(16) __nv_bfloat16 g_act_lo[(size_t)BT * 1024];
__device__ __align__(16) __nv_bfloat16 g_w1_hi [(size_t)IN_PROJ_PAD * 1024];
__device__ __align__(16) __nv_bfloat16 g_w1_lo [(size_t)IN_PROJ_PAD * 1024];
__device__ __align__(16) __nv_bfloat16 g_w2_hi [(size_t)1024 * 1024];
__device__ __align__(16) __nv_bfloat16 g_w2_lo [(size_t)1024 * 1024];

// ===========================================================================
// split-bf16 conversion
// ===========================================================================
__global__ void cvt_split(const float* __restrict__ s,
                          __nv_bfloat16* __restrict__ hi,
                          __nv_bfloat16* __restrict__ lo,
                          int n_real, int n_total)
{
    int i = (blockIdx.x * 256 + threadIdx.x) * 4;
    if (i >= n_total) return;
    __nv_bfloat16 h[4], l[4];
    if (i < n_real) {
        float4 v = *(const float4*)(s + i);
        float a[4] = {v.x, v.y, v.z, v.w};
#pragma unroll
        for (int j = 0; j < 4; j++) {
            h[j] = __float2bfloat16(a[j]);
            l[j] = __float2bfloat16(a[j] - __bfloat162float(h[j]));
        }
    } else {
#pragma unroll
        for (int j = 0; j < 4; j++) { h[j] = __float2bfloat16(0.f); l[j] = h[j]; }
    }
    *(__nv_bfloat162*)(hi + i)     = __nv_bfloat162(h[0], h[1]);
    *(__nv_bfloat162*)(hi + i + 2) = __nv_bfloat162(h[2], h[3]);
    *(__nv_bfloat162*)(lo + i)     = __nv_bfloat162(l[0], l[1]);
    *(__nv_bfloat162*)(lo + i + 2) = __nv_bfloat162(l[2], l[3]);
}

// ===========================================================================
// shared helpers
// ===========================================================================
__device__ __forceinline__ uint32_t smem_u32(const void* p) {
    uint32_t a;
    asm("{ .reg .u64 t; cvta.to.shared.u64 t, %1; cvt.u32.u64 %0, t; }"
        : "=r"(a) : "l"(p));
    return a;
}
__device__ __forceinline__ uint32_t sw128(uint32_t off) {
    return off ^ ((off >> 3) & 0x70);
}
__device__ __forceinline__ void ldmat4(uint32_t& r0, uint32_t& r1,
                                       uint32_t& r2, uint32_t& r3, uint32_t a) {
    asm volatile("ldmatrix.sync.aligned.m8n8.x4.shared.b16 {%0,%1,%2,%3}, [%4];"
                 : "=r"(r0), "=r"(r1), "=r"(r2), "=r"(r3) : "r"(a));
}
__device__ __forceinline__ void mma16816(float* c, const uint32_t* a,
                                         uint32_t b0, uint32_t b1) {
    asm volatile(
        "mma.sync.aligned.m16n8k16.row.col.f32.bf16.bf16.f32 "
        "{%0,%1,%2,%3}, {%4,%5,%6,%7}, {%8,%9}, {%0,%1,%2,%3};"
        : "+f"(c[0]), "+f"(c[1]), "+f"(c[2]), "+f"(c[3])
        : "r"(a[0]), "r"(a[1]), "r"(a[2]), "r"(a[3]), "r"(b0), "r"(b1));
}
__device__ __forceinline__ void cp16(uint32_t dst, const void* src) {
    asm volatile("cp.async.cg.shared.global [%0], [%1], 16;"
                 :: "r"(dst), "l"(src));
}

// ===========================================================================
// HMMA split-bf16 GEMM (NT), cp.async 2-stage pipeline, 512 threads (R9 best)
// ===========================================================================
__device__ __forceinline__ void load_tile_async512(
    const __nv_bfloat16* __restrict__ g, int row0, int K, int k0,
    uint32_t sbase, int tid)
{
#pragma unroll
    for (int j = 0; j < 2; j++) {
        int u = tid + 512 * j;
        int row = u >> 3, cg = u & 7;
        uint32_t off = (uint32_t)(row * 128 + cg * 16);
        cp16(sbase + sw128(off), g + (size_t)(row0 + row) * K + k0 + cg * 8);
    }
}

#define STAGE_SZ 65536u
#define GEMM_SMEM (2 * 65536)
__global__ __launch_bounds__(512, 1)
void gemm_hmma(const __nv_bfloat16* __restrict__ Ahi,
               const __nv_bfloat16* __restrict__ Alo,
               const __nv_bfloat16* __restrict__ Bhi,
               const __nv_bfloat16* __restrict__ Blo,
               float* __restrict__ C, int K, int Nreal, int ldc)
{
    extern __shared__ char sm[];
    const uint32_t s0 = smem_u32(sm);
    const int tid = threadIdx.x;
    const int wid = tid >> 5, lid = tid & 31;
    const int wm = wid & 3, wn = wid >> 2;
    const int m0 = blockIdx.y * 128, n0 = blockIdx.x * 128;

    float acc[2][4][4];
#pragma unroll
    for (int i = 0; i < 2; i++)
#pragma unroll
        for (int j = 0; j < 4; j++)
#pragma unroll
            for (int q = 0; q < 4; q++) acc[i][j][q] = 0.f;

    const int lrow = lid & 15;
    const int lkb  = (lid >> 4) * 16;
    const int NKC = K >> 6;

    {
        uint32_t base = s0;
        load_tile_async512(Ahi, m0, K, 0, base,             tid);
        load_tile_async512(Alo, m0, K, 0, base + 16384,     tid);
        load_tile_async512(Bhi, n0, K, 0, base + 32768,     tid);
        load_tile_async512(Blo, n0, K, 0, base + 49152,     tid);
        asm volatile("cp.async.commit_group;");
    }

    for (int kc = 0; kc < NKC; kc++) {
        if (kc + 1 < NKC) {
            uint32_t base = s0 + ((kc + 1) & 1) * STAGE_SZ;
            int k0 = (kc + 1) << 6;
            load_tile_async512(Ahi, m0, K, k0, base,         tid);
            load_tile_async512(Alo, m0, K, k0, base + 16384, tid);
            load_tile_async512(Bhi, n0, K, k0, base + 32768, tid);
            load_tile_async512(Blo, n0, K, k0, base + 49152, tid);
            asm volatile("cp.async.commit_group;");
            asm volatile("cp.async.wait_group 1;");
        } else {
            asm volatile("cp.async.wait_group 0;");
        }
        __syncthreads();

        const uint32_t sAH = s0 + (kc & 1) * STAGE_SZ;
        const uint32_t sAL = sAH + 16384;
        const uint32_t sBH = sAH + 32768;
        const uint32_t sBL = sAH + 49152;
#pragma unroll
        for (int ks = 0; ks < 4; ks++) {
            const int kb = ks * 32 + lkb;
            uint32_t bh[2][4], bl[2][4];
#pragma unroll
            for (int g2 = 0; g2 < 2; g2++) {
                uint32_t off = (uint32_t)((wn * 32 + g2 * 16 + lrow) * 128 + kb);
                ldmat4(bh[g2][0], bh[g2][1], bh[g2][2], bh[g2][3], sBH + sw128(off));
                ldmat4(bl[g2][0], bl[g2][1], bl[g2][2], bl[g2][3], sBL + sw128(off));
            }
#pragma unroll
            for (int mi = 0; mi < 2; mi++) {
                uint32_t ah[4], al[4];
                uint32_t off = (uint32_t)((wm * 32 + mi * 16 + lrow) * 128 + kb);
                ldmat4(ah[0], ah[1], ah[2], ah[3], sAH + sw128(off));
                ldmat4(al[0], al[1], al[2], al[3], sAL + sw128(off));
#pragma unroll
                for (int ni = 0; ni < 4; ni++) {
                    const int g2 = ni >> 1, pt = ni & 1;
                    mma16816(acc[mi][ni], ah, bh[g2][pt], bh[g2][pt + 2]);
                    mma16816(acc[mi][ni], ah, bl[g2][pt], bl[g2][pt + 2]);
                    mma16816(acc[mi][ni], al, bh[g2][pt], bh[g2][pt + 2]);
                }
            }
        }
        __syncthreads();
    }

    const int crow = lid >> 2, ccol = (lid & 3) * 2;
#pragma unroll
    for (int mi = 0; mi < 2; mi++) {
#pragma unroll
        for (int ni = 0; ni < 4; ni++) {
            int n = n0 + wn * 32 + ni * 8 + ccol;
            if (n >= Nreal) continue;
            int m = m0 + wm * 32 + mi * 16 + crow;
            *(float2*)(C + (size_t)m * ldc + n) =
                make_float2(acc[mi][ni][0], acc[mi][ni][1]);
            *(float2*)(C + (size_t)(m + 8) * ldc + n) =
                make_float2(acc[mi][ni][2], acc[mi][ni][3]);
        }
    }
}

// ---------------------------------------------------------------------------
// Fused conv helper: 4-tap causal depthwise conv of 4 consecutive channels
// at within-batch time tseq, reading raw GEMM output. Order: bias, k=0..3.
// ---------------------------------------------------------------------------
__device__ __forceinline__ float4 conv4(const float* __restrict__ xb,
                                        int tseq, int ch,
                                        const float w[4][4], float4 bias)
{
    float4 a = bias;
#pragma unroll
    for (int k = 0; k < 4; k++) {
        int tt = tseq - 3 + k;
        if (tt >= 0) {
            float4 v = *(const float4*)(xb + (size_t)tt * IN_PROJ + ch);
            a.x += w[0][k] * v.x; a.y += w[1][k] * v.y;
            a.z += w[2][k] * v.z; a.w += w[3][k] * v.w;
        }
    }
    return a;
}
__device__ __forceinline__ void load_w4(const float* __restrict__ cw, int ch,
                                        float w[4][4])
{
#pragma unroll
    for (int i = 0; i < 4; i++)
#pragma unroll
        for (int k = 0; k < 4; k++) w[i][k] = cw[(ch + i) * 4 + k];
}

// ---------------------------------------------------------------------------
// Chunk kernel (R9 structure, conv fused in). per (h, c, b). 153,088 B smem.
// ---------------------------------------------------------------------------
#define CTS 132
#define XSS 33
__global__ __launch_bounds__(256, 1) void chunk_kernel(
    const float* __restrict__ cw, const float* __restrict__ cb)
{
    extern __shared__ float smf[];
    float* Ct   = smf;
    float* Btm  = Ct + 64 * CTS;
    float* Xs   = Btm + 64 * CTS;
    float* Ps   = Xs + 128 * XSS;
    float* acum = Ps + 128 * CTS;
    float* darr = acum + CHUNK_;

    const int tid = threadIdx.x;
    const int h = blockIdx.x, c = blockIdx.y, b = blockIdx.z;
    const size_t bt0 = (size_t)b * SEQ + (size_t)c * CHUNK_;
    const int chunk_id = (b * NC_ + c) * NV_ + h;
    const float* xb = g_xbcza + (size_t)b * SEQ * IN_PROJ;
    const int tseq0 = c * CHUNK_;

    if (tid < 128) {
        float a = g_xbcza[(bt0 + tid) * IN_PROJ + (CONV_DIM + D_INNER) + h];
        darr[tid] = (a > 20.f) ? a : log1pf(expf(a));
    }
    __syncthreads();
    if (tid < 32) {
        float v0 = darr[tid*4+0], v1 = darr[tid*4+1];
        float v2 = darr[tid*4+2], v3 = darr[tid*4+3];
        float s1 = v0+v1, s2 = s1+v2, s3 = s2+v3;
        float t = s3;
#pragma unroll
        for (int o = 1; o < 32; o <<= 1) {
            float u2 = __shfl_up_sync(0xffffffffu, t, o);
            if (tid >= o) t += u2;
        }
        float base = t - s3;
        acum[tid*4+0] = -(base+v0); acum[tid*4+1] = -(base+s1);
        acum[tid*4+2] = -(base+s2); acum[tid*4+3] = -(base+s3);
    }
    __syncthreads();
    const float alast = acum[127];
    if (tid < 128) {
        darr[tid] = __expf(alast - acum[tid]);
        g_acum[(size_t)chunk_id * CHUNK_ + tid] = acum[tid];
    }
    if (tid == 0) g_dc[chunk_id] = __expf(alast);

    // C and B with fused conv (weights hoisted; col fixed per thread)
    {
        const int col = (tid & 15) * 4;
        const int chC = D_INNER + NQK*DSTATE + h*DSTATE + col;
        const int chB = D_INNER + h*DSTATE + col;
        float wC[4][4], wB[4][4];
        load_w4(cw, chC, wC);
        load_w4(cw, chB, wB);
        float4 bC = *(const float4*)(cb + chC);
        float4 bB = *(const float4*)(cb + chB);
#pragma unroll
        for (int pass = 0; pass < 8; pass++) {
            int r = pass * 16 + (tid >> 4);
            float4 aC = conv4(xb, tseq0 + r, chC, wC, bC);
            float4 aB = conv4(xb, tseq0 + r, chB, wB, bB);
            Ct[(col+0)*CTS + r] = aC.x; Ct[(col+1)*CTS + r] = aC.y;
            Ct[(col+2)*CTS + r] = aC.z; Ct[(col+3)*CTS + r] = aC.w;
            Btm[(col+0)*CTS + r] = aB.x; Btm[(col+1)*CTS + r] = aB.y;
            Btm[(col+2)*CTS + r] = aB.z; Btm[(col+3)*CTS + r] = aB.w;
        }
    }
    // X with fused conv
    {
        const int col = (tid & 7) * 4;
        const int chX = h*HEADDIM + col;
        float wX[4][4];
        load_w4(cw, chX, wX);
        float4 bX = *(const float4*)(cb + chX);
#pragma unroll
        for (int pass = 0; pass < 4; pass++) {
            int r = pass * 32 + (tid >> 3);
            float4 aX = conv4(xb, tseq0 + r, chX, wX, bX);
            Xs[r*XSS + col+0] = aX.x; Xs[r*XSS + col+1] = aX.y;
            Xs[r*XSS + col+2] = aX.z; Xs[r*XSS + col+3] = aX.w;
        }
    }
    __syncthreads();

    const int ty = tid >> 4, tx = tid & 15;
    float accG[8][8];
#pragma unroll
    for (int i = 0; i < 8; i++)
#pragma unroll
        for (int j = 0; j < 8; j++) accG[i][j] = 0.f;
#pragma unroll 4
    for (int n = 0; n < 64; n++) {
        float4 a0 = *(const float4*)&Ct[n*CTS + ty*8];
        float4 a1 = *(const float4*)&Ct[n*CTS + ty*8 + 4];
        float4 b0 = *(const float4*)&Btm[n*CTS + tx*8];
        float4 b1 = *(const float4*)&Btm[n*CTS + tx*8 + 4];
        float av[8] = {a0.x,a0.y,a0.z,a0.w,a1.x,a1.y,a1.z,a1.w};
        float bv[8] = {b0.x,b0.y,b0.z,b0.w,b1.x,b1.y,b1.z,b1.w};
#pragma unroll
        for (int i = 0; i < 8; i++)
#pragma unroll
            for (int j = 0; j < 8; j++) accG[i][j] += av[i] * bv[j];
    }
    float al[8], asv[8];
#pragma unroll
    for (int i = 0; i < 8; i++) al[i] = acum[ty*8 + i];
#pragma unroll
    for (int j = 0; j < 8; j++) asv[j] = acum[tx*8 + j];
#pragma unroll
    for (int i = 0; i < 8; i++) {
        int l = ty*8 + i;
#pragma unroll
        for (int j = 0; j < 8; j++) {
            int s = tx*8 + j;
            accG[i][j] = (s <= l) ? accG[i][j] * __expf(al[i] - asv[j]) : 0.f;
        }
        *(float4*)&Ps[l*CTS + tx*8]     = make_float4(accG[i][0],accG[i][1],accG[i][2],accG[i][3]);
        *(float4*)&Ps[l*CTS + tx*8 + 4] = make_float4(accG[i][4],accG[i][5],accG[i][6],accG[i][7]);
    }
    __syncthreads();

    {
        const int lq = tid >> 3, pq = tid & 7;
        float acc[4][4] = {};
        for (int s = 0; s < 128; s++) {
            float bf0 = Xs[s*XSS + pq*4+0];
            float bf1 = Xs[s*XSS + pq*4+1];
            float bf2 = Xs[s*XSS + pq*4+2];
            float bf3 = Xs[s*XSS + pq*4+3];
#pragma unroll
            for (int i = 0; i < 4; i++) {
                float a = Ps[(lq*4+i)*CTS + s];
                acc[i][0] += a*bf0; acc[i][1] += a*bf1;
                acc[i][2] += a*bf2; acc[i][3] += a*bf3;
            }
        }
#pragma unroll
        for (int i = 0; i < 4; i++) {
            size_t row = (bt0 + lq*4 + i) * D_INNER + h*HEADDIM + pq*4;
            *(float4*)&g_y[row] = make_float4(acc[i][0],acc[i][1],acc[i][2],acc[i][3]);
        }
    }

    {
        const int n  = tid >> 2;
        const int pg = tid & 3;
        float acc[8] = {};
        for (int l = 0; l < 128; l++) {
            float bv = Btm[n*CTS + l] * darr[l];
#pragma unroll
            for (int j = 0; j < 8; j++) acc[j] += bv * Xs[l*XSS + pg*8 + j];
        }
        size_t base = (size_t)chunk_id * (HEADDIM * DSTATE);
#pragma unroll
        for (int j = 0; j < 8; j++)
            g_states[base + (size_t)(pg*8 + j) * DSTATE + n] = acc[j];
    }
}

// ---------------------------------------------------------------------------
__global__ void scan_kernel()
{
    const int bh = blockIdx.x;
    const int b = bh >> 5, h = bh & 31;
    const int e = threadIdx.x * 4;
    float4 S = make_float4(0.f,0.f,0.f,0.f);
    for (int c = 0; c < NC_; c++) {
        const int cid = (b * NC_ + c) * NV_ + h;
        size_t base = (size_t)cid * (HEADDIM * DSTATE) + e;
        *(float4*)&g_prevs[base] = S;
        float4 st = *(const float4*)&g_states[base];
        float d = g_dc[cid];
        S.x = S.x*d + st.x; S.y = S.y*d + st.y;
        S.z = S.z*d + st.z; S.w = S.w*d + st.w;
    }
}

// ---------------------------------------------------------------------------
// Y_off + D*x + SiLU gating (conv fused for C and x).
// ---------------------------------------------------------------------------
__global__ __launch_bounds__(256) void yoff_kernel(
    const float* __restrict__ cw, const float* __restrict__ cb,
    const float* __restrict__ z_bias, const float* __restrict__ Dvec)
{
    __shared__ float Cs[128 * 65];
    __shared__ float Pv[32 * 65];
    __shared__ float ea[128];
    const int tid = threadIdx.x;
    const int h = blockIdx.x, c = blockIdx.y, b = blockIdx.z;
    const size_t bt0 = (size_t)b * SEQ + (size_t)c * CHUNK_;
    const int chunk_id = (b * NC_ + c) * NV_ + h;
    const float* xb = g_xbcza + (size_t)b * SEQ * IN_PROJ;
    const int tseq0 = c * CHUNK_;

    if (tid < 128) ea[tid] = __expf(g_acum[(size_t)chunk_id * CHUNK_ + tid]);

    // Cs with fused conv (col fixed per thread within each pass set)
    {
        const int col = (tid & 15) * 4;
        const int chC = D_INNER + NQK*DSTATE + h*DSTATE + col;
        float wC[4][4];
        load_w4(cw, chC, wC);
        float4 bC = *(const float4*)(cb + chC);
#pragma unroll
        for (int pass = 0; pass < 8; pass++) {
            int r = pass * 16 + (tid >> 4);
            float4 v = conv4(xb, tseq0 + r, chC, wC, bC);
            Cs[r*65 + col+0] = v.x; Cs[r*65 + col+1] = v.y;
            Cs[r*65 + col+2] = v.z; Cs[r*65 + col+3] = v.w;
        }
    }
    size_t pbase = (size_t)chunk_id * (HEADDIM * DSTATE);
#pragma unroll
    for (int pass = 0; pass < 2; pass++) {
        int idx = pass * 256 + tid;
        int p = idx >> 4, col = (idx & 15) * 4;
        float4 v = *(const float4*)(g_prevs + pbase + (size_t)p * DSTATE + col);
        Pv[p*65 + col+0] = v.x; Pv[p*65 + col+1] = v.y;
        Pv[p*65 + col+2] = v.z; Pv[p*65 + col+3] = v.w;
    }
    __syncthreads();

    const int l = tid >> 1;
    const int p0 = (tid & 1) * 16;
    const float e = ea[l];
    float acc[16];
#pragma unroll
    for (int j = 0; j < 16; j++) acc[j] = 0.f;
    for (int n = 0; n < 64; n++) {
        float cv = Cs[l*65 + n];
#pragma unroll
        for (int j = 0; j < 16; j++) acc[j] += cv * Pv[(p0+j)*65 + n];
    }
    // x via fused conv: 16 channels in 4 groups of 4
    const int chbase = h * HEADDIM + p0;
    float xv[16];
    {
        const int tseq = tseq0 + l;
#pragma unroll
        for (int g = 0; g < 4; g++) {
            int ch = chbase + g * 4;
            float wX[4][4];
            load_w4(cw, ch, wX);
            float4 bX = *(const float4*)(cb + ch);
            float4 a = conv4(xb, tseq, ch, wX, bX);
            xv[g*4+0] = a.x; xv[g*4+1] = a.y; xv[g*4+2] = a.z; xv[g*4+3] = a.w;
        }
    }
    const float Dh = Dvec[h];
#pragma unroll
    for (int j = 0; j < 16; j++) {
        int ch = chbase + j;
        size_t oidx = (bt0 + l) * D_INNER + ch;
        float zd = g_xbcza[(bt0 + l) * IN_PROJ + CONV_DIM + ch] + z_bias[ch];
        float sg = zd / (1.f + __expf(-zd));
        g_y[oidx] = (g_y[oidx] + e * acc[j] + Dh * xv[j]) * sg;
    }
}

// ---------------------------------------------------------------------------
extern "C" void kernel_launch(void* const* d_in, const int* in_sizes, int n_in,
                              void* d_out, int out_size)
{
    const float* u      = (const float*)d_in[0];
    const float* W_in   = (const float*)d_in[1];
    const float* conv_w = (const float*)d_in[2];
    const float* conv_b = (const float*)d_in[3];
    const float* z_bias = (const float*)d_in[4];
    const float* Dvec   = (const float*)d_in[5];
    const float* W_out  = (const float*)d_in[6];
    float* out = (float*)d_out;

    float *p_xbcza = nullptr, *p_y = nullptr;
    __nv_bfloat16 *p_ah, *p_al, *p_w1h, *p_w1l, *p_w2h, *p_w2l;
    cudaGetSymbolAddress((void**)&p_xbcza, g_xbcza);
    cudaGetSymbolAddress((void**)&p_y, g_y);
    cudaGetSymbolAddress((void**)&p_ah, g_act_hi);
    cudaGetSymbolAddress((void**)&p_al, g_act_lo);
    cudaGetSymbolAddress((void**)&p_w1h, g_w1_hi);
    cudaGetSymbolAddress((void**)&p_w1l, g_w1_lo);
    cudaGetSymbolAddress((void**)&p_w2h, g_w2_hi);
    cudaGetSymbolAddress((void**)&p_w2l, g_w2_lo);

    static int attr_set = 0;
    if (!attr_set) {
        cudaFuncSetAttribute(gemm_hmma,
            cudaFuncAttributeMaxDynamicSharedMemorySize, GEMM_SMEM);
        size_t csm = (64*CTS + 64*CTS + 128*XSS + 128*CTS + 2*CHUNK_) * sizeof(float);
        cudaFuncSetAttribute(chunk_kernel,
            cudaFuncAttributeMaxDynamicSharedMemorySize, (int)csm);
        attr_set = 1;
    }

    // split conversions
    cvt_split<<<(BT*1024)/1024, 256>>>(u, p_ah, p_al, BT*1024, BT*1024);
    cvt_split<<<(IN_PROJ_PAD*1024)/1024, 256>>>(W_in, p_w1h, p_w1l,
                                                IN_PROJ*1024, IN_PROJ_PAD*1024);
    cvt_split<<<(1024*1024)/1024, 256>>>(W_out, p_w2h, p_w2l, 1024*1024, 1024*1024);

    // in-proj
    {
        dim3 grid(IN_PROJ_PAD / 128, BT / 128);
        gemm_hmma<<<grid, 512, GEMM_SMEM>>>(p_ah, p_al, p_w1h, p_w1l,
                                            p_xbcza, D_MODEL, IN_PROJ, IN_PROJ);
    }
    // chunk (conv fused)
    {
        size_t csm = (64*CTS + 64*CTS + 128*XSS + 128*CTS + 2*CHUNK_) * sizeof(float);
        dim3 grid(NV_, NC_, BATCH);
        chunk_kernel<<<grid, 256, csm>>>(conv_w, conv_b);
    }
    scan_kernel<<<BATCH * NV_, 512>>>();
    // y_off (conv fused)
    {
        dim3 grid(NV_, NC_, BATCH);
        yoff_kernel<<<grid, 256>>>(conv_w, conv_b, z_bias, Dvec);
    }
    // out-proj
    cvt_split<<<(BT*1024)/1024, 256>>>(p_y, p_ah, p_al, BT*1024, BT*1024);
    {
        dim3 grid(D_MODEL / 128, BT / 128);
        gemm_hmma<<<grid, 512, GEMM_SMEM>>>(p_ah, p_al, p_w2h, p_w2l,
                                            out, D_INNER, D_MODEL, D_MODEL);
    }
}

// round 14
// speedup vs baseline: 2.5844x; 1.6890x over previous
#include <cuda_runtime.h>
#include <cuda_fp16.h>
#include <cstdint>
#include <cstddef>

#define D_MODEL   1024
#define D_INNER   1024
#define NQK       32
#define NV_       32
#define DSTATE    64
#define DCONV     4
#define CHUNK_    128
#define CONV_DIM  5120
#define HEADDIM   32
#define IN_PROJ   6176
#define IN_PROJ_PAD 6272
#define BATCH     2
#define SEQ       8192
#define BT        16384
#define NC_       64

// ---- scratch (device globals) ----
__device__ __align__(16) float g_xbcza[(size_t)BT * IN_PROJ];
__device__ __align__(16) float g_y[(size_t)BT * D_INNER];
__device__ __align__(16) float g_states[(size_t)BATCH * NC_ * NV_ * HEADDIM * DSTATE];
__device__ __align__(16) float g_prevs [(size_t)BATCH * NC_ * NV_ * HEADDIM * DSTATE];
__device__ __align__(16) float g_acum  [(size_t)BATCH * NC_ * NV_ * CHUNK_];
__device__ __align__(16) float g_dc    [BATCH * NC_ * NV_];
__device__ __align__(16) __half g_act[(size_t)BT * 1024];
__device__ __align__(16) __half g_w1 [(size_t)IN_PROJ_PAD * 1024];
__device__ __align__(16) __half g_w2 [(size_t)1024 * 1024];

// ===========================================================================
// fp16 conversion (RN)
// ===========================================================================
__global__ void cvt_f16(const float* __restrict__ s,
                        __half* __restrict__ d,
                        int n_real, int n_total)
{
    int i = (blockIdx.x * 256 + threadIdx.x) * 4;
    if (i >= n_total) return;
    __half h[4];
    if (i < n_real) {
        float4 v = *(const float4*)(s + i);
        h[0] = __float2half_rn(v.x); h[1] = __float2half_rn(v.y);
        h[2] = __float2half_rn(v.z); h[3] = __float2half_rn(v.w);
    } else {
        h[0] = h[1] = h[2] = h[3] = __float2half_rn(0.f);
    }
    *(uint2*)(d + i) = make_uint2(*(uint32_t*)&h[0], *(uint32_t*)&h[2]);
}

// ===========================================================================
// shared helpers
// ===========================================================================
__device__ __forceinline__ uint32_t smem_u32(const void* p) {
    uint32_t a;
    asm("{ .reg .u64 t; cvta.to.shared.u64 t, %1; cvt.u32.u64 %0, t; }"
        : "=r"(a) : "l"(p));
    return a;
}
__device__ __forceinline__ uint32_t sw128(uint32_t off) {
    return off ^ ((off >> 3) & 0x70);
}
__device__ __forceinline__ void ldmat4(uint32_t& r0, uint32_t& r1,
                                       uint32_t& r2, uint32_t& r3, uint32_t a) {
    asm volatile("ldmatrix.sync.aligned.m8n8.x4.shared.b16 {%0,%1,%2,%3}, [%4];"
                 : "=r"(r0), "=r"(r1), "=r"(r2), "=r"(r3) : "r"(a));
}
__device__ __forceinline__ void mma16816h(float* c, const uint32_t* a,
                                          uint32_t b0, uint32_t b1) {
    asm volatile(
        "mma.sync.aligned.m16n8k16.row.col.f32.f16.f16.f32 "
        "{%0,%1,%2,%3}, {%4,%5,%6,%7}, {%8,%9}, {%0,%1,%2,%3};"
        : "+f"(c[0]), "+f"(c[1]), "+f"(c[2]), "+f"(c[3])
        : "r"(a[0]), "r"(a[1]), "r"(a[2]), "r"(a[3]), "r"(b0), "r"(b1));
}
__device__ __forceinline__ void cp16(uint32_t dst, const void* src) {
    asm volatile("cp.async.cg.shared.global [%0], [%1], 16;"
                 :: "r"(dst), "l"(src));
}

// ===========================================================================
// HMMA fp16 single-pass GEMM (NT), cp.async 2-stage pipeline, 512 threads
// ===========================================================================
__device__ __forceinline__ void load_tile_async512h(
    const __half* __restrict__ g, int row0, int K, int k0,
    uint32_t sbase, int tid)
{
#pragma unroll
    for (int j = 0; j < 2; j++) {
        int u = tid + 512 * j;
        int row = u >> 3, cg = u & 7;
        uint32_t off = (uint32_t)(row * 128 + cg * 16);
        cp16(sbase + sw128(off), g + (size_t)(row0 + row) * K + k0 + cg * 8);
    }
}

#define STAGE_SZ 32768u
#define GEMM_SMEM (2 * 32768)
__global__ __launch_bounds__(512, 1)
void gemm_hmma(const __half* __restrict__ A,
               const __half* __restrict__ B,
               float* __restrict__ C, int K, int Nreal, int ldc)
{
    extern __shared__ char sm[];
    const uint32_t s0 = smem_u32(sm);
    const int tid = threadIdx.x;
    const int wid = tid >> 5, lid = tid & 31;
    const int wm = wid & 3, wn = wid >> 2;
    const int m0 = blockIdx.y * 128, n0 = blockIdx.x * 128;

    float acc[2][4][4];
#pragma unroll
    for (int i = 0; i < 2; i++)
#pragma unroll
        for (int j = 0; j < 4; j++)
#pragma unroll
            for (int q = 0; q < 4; q++) acc[i][j][q] = 0.f;

    const int lrow = lid & 15;
    const int lkb  = (lid >> 4) * 16;
    const int NKC = K >> 6;

    {
        load_tile_async512h(A, m0, K, 0, s0,         tid);
        load_tile_async512h(B, n0, K, 0, s0 + 16384, tid);
        asm volatile("cp.async.commit_group;");
    }

    for (int kc = 0; kc < NKC; kc++) {
        if (kc + 1 < NKC) {
            uint32_t base = s0 + ((kc + 1) & 1) * STAGE_SZ;
            int k0 = (kc + 1) << 6;
            load_tile_async512h(A, m0, K, k0, base,         tid);
            load_tile_async512h(B, n0, K, k0, base + 16384, tid);
            asm volatile("cp.async.commit_group;");
            asm volatile("cp.async.wait_group 1;");
        } else {
            asm volatile("cp.async.wait_group 0;");
        }
        __syncthreads();

        const uint32_t sA = s0 + (kc & 1) * STAGE_SZ;
        const uint32_t sB = sA + 16384;
#pragma unroll
        for (int ks = 0; ks < 4; ks++) {
            const int kb = ks * 32 + lkb;
            uint32_t bh[2][4];
#pragma unroll
            for (int g2 = 0; g2 < 2; g2++) {
                uint32_t off = (uint32_t)((wn * 32 + g2 * 16 + lrow) * 128 + kb);
                ldmat4(bh[g2][0], bh[g2][1], bh[g2][2], bh[g2][3], sB + sw128(off));
            }
#pragma unroll
            for (int mi = 0; mi < 2; mi++) {
                uint32_t ah[4];
                uint32_t off = (uint32_t)((wm * 32 + mi * 16 + lrow) * 128 + kb);
                ldmat4(ah[0], ah[1], ah[2], ah[3], sA + sw128(off));
#pragma unroll
                for (int ni = 0; ni < 4; ni++) {
                    const int g2 = ni >> 1, pt = ni & 1;
                    mma16816h(acc[mi][ni], ah, bh[g2][pt], bh[g2][pt + 2]);
                }
            }
        }
        __syncthreads();
    }

    const int crow = lid >> 2, ccol = (lid & 3) * 2;
#pragma unroll
    for (int mi = 0; mi < 2; mi++) {
#pragma unroll
        for (int ni = 0; ni < 4; ni++) {
            int n = n0 + wn * 32 + ni * 8 + ccol;
            if (n >= Nreal) continue;
            int m = m0 + wm * 32 + mi * 16 + crow;
            *(float2*)(C + (size_t)m * ldc + n) =
                make_float2(acc[mi][ni][0], acc[mi][ni][1]);
            *(float2*)(C + (size_t)(m + 8) * ldc + n) =
                make_float2(acc[mi][ni][2], acc[mi][ni][3]);
        }
    }
}

// ---------------------------------------------------------------------------
// Fused conv helper (R13): bias, taps k=0..3 order.
// ---------------------------------------------------------------------------
__device__ __forceinline__ float4 conv4(const float* __restrict__ xb,
                                        int tseq, int ch,
                                        const float w[4][4], float4 bias)
{
    float4 a = bias;
#pragma unroll
    for (int k = 0; k < 4; k++) {
        int tt = tseq - 3 + k;
        if (tt >= 0) {
            float4 v = *(const float4*)(xb + (size_t)tt * IN_PROJ + ch);
            a.x += w[0][k] * v.x; a.y += w[1][k] * v.y;
            a.z += w[2][k] * v.z; a.w += w[3][k] * v.w;
        }
    }
    return a;
}
__device__ __forceinline__ void load_w4(const float* __restrict__ cw, int ch,
                                        float w[4][4])
{
#pragma unroll
    for (int i = 0; i < 4; i++)
#pragma unroll
        for (int k = 0; k < 4; k++) w[i][k] = cw[(ch + i) * 4 + k];
}

// ---------------------------------------------------------------------------
// Chunk kernel (R13, conv fused). per (h, c, b). 153,088 B smem.
// ---------------------------------------------------------------------------
#define CTS 132
#define XSS 33
__global__ __launch_bounds__(256, 1) void chunk_kernel(
    const float* __restrict__ cw, const float* __restrict__ cb)
{
    extern __shared__ float smf[];
    float* Ct   = smf;
    float* Btm  = Ct + 64 * CTS;
    float* Xs   = Btm + 64 * CTS;
    float* Ps   = Xs + 128 * XSS;
    float* acum = Ps + 128 * CTS;
    float* darr = acum + CHUNK_;

    const int tid = threadIdx.x;
    const int h = blockIdx.x, c = blockIdx.y, b = blockIdx.z;
    const size_t bt0 = (size_t)b * SEQ + (size_t)c * CHUNK_;
    const int chunk_id = (b * NC_ + c) * NV_ + h;
    const float* xb = g_xbcza + (size_t)b * SEQ * IN_PROJ;
    const int tseq0 = c * CHUNK_;

    if (tid < 128) {
        float a = g_xbcza[(bt0 + tid) * IN_PROJ + (CONV_DIM + D_INNER) + h];
        darr[tid] = (a > 20.f) ? a : log1pf(expf(a));
    }
    __syncthreads();
    if (tid < 32) {
        float v0 = darr[tid*4+0], v1 = darr[tid*4+1];
        float v2 = darr[tid*4+2], v3 = darr[tid*4+3];
        float s1 = v0+v1, s2 = s1+v2, s3 = s2+v3;
        float t = s3;
#pragma unroll
        for (int o = 1; o < 32; o <<= 1) {
            float u2 = __shfl_up_sync(0xffffffffu, t, o);
            if (tid >= o) t += u2;
        }
        float base = t - s3;
        acum[tid*4+0] = -(base+v0); acum[tid*4+1] = -(base+s1);
        acum[tid*4+2] = -(base+s2); acum[tid*4+3] = -(base+s3);
    }
    __syncthreads();
    const float alast = acum[127];
    if (tid < 128) {
        darr[tid] = __expf(alast - acum[tid]);
        g_acum[(size_t)chunk_id * CHUNK_ + tid] = acum[tid];
    }
    if (tid == 0) g_dc[chunk_id] = __expf(alast);

    {
        const int col = (tid & 15) * 4;
        const int chC = D_INNER + NQK*DSTATE + h*DSTATE + col;
        const int chB = D_INNER + h*DSTATE + col;
        float wC[4][4], wB[4][4];
        load_w4(cw, chC, wC);
        load_w4(cw, chB, wB);
        float4 bC = *(const float4*)(cb + chC);
        float4 bB = *(const float4*)(cb + chB);
#pragma unroll
        for (int pass = 0; pass < 8; pass++) {
            int r = pass * 16 + (tid >> 4);
            float4 aC = conv4(xb, tseq0 + r, chC, wC, bC);
            float4 aB = conv4(xb, tseq0 + r, chB, wB, bB);
            Ct[(col+0)*CTS + r] = aC.x; Ct[(col+1)*CTS + r] = aC.y;
            Ct[(col+2)*CTS + r] = aC.z; Ct[(col+3)*CTS + r] = aC.w;
            Btm[(col+0)*CTS + r] = aB.x; Btm[(col+1)*CTS + r] = aB.y;
            Btm[(col+2)*CTS + r] = aB.z; Btm[(col+3)*CTS + r] = aB.w;
        }
    }
    {
        const int col = (tid & 7) * 4;
        const int chX = h*HEADDIM + col;
        float wX[4][4];
        load_w4(cw, chX, wX);
        float4 bX = *(const float4*)(cb + chX);
#pragma unroll
        for (int pass = 0; pass < 4; pass++) {
            int r = pass * 32 + (tid >> 3);
            float4 aX = conv4(xb, tseq0 + r, chX, wX, bX);
            Xs[r*XSS + col+0] = aX.x; Xs[r*XSS + col+1] = aX.y;
            Xs[r*XSS + col+2] = aX.z; Xs[r*XSS + col+3] = aX.w;
        }
    }
    __syncthreads();

    const int ty = tid >> 4, tx = tid & 15;
    float accG[8][8];
#pragma unroll
    for (int i = 0; i < 8; i++)
#pragma unroll
        for (int j = 0; j < 8; j++) accG[i][j] = 0.f;
#pragma unroll 4
    for (int n = 0; n < 64; n++) {
        float4 a0 = *(const float4*)&Ct[n*CTS + ty*8];
        float4 a1 = *(const float4*)&Ct[n*CTS + ty*8 + 4];
        float4 b0 = *(const float4*)&Btm[n*CTS + tx*8];
        float4 b1 = *(const float4*)&Btm[n*CTS + tx*8 + 4];
        float av[8] = {a0.x,a0.y,a0.z,a0.w,a1.x,a1.y,a1.z,a1.w};
        float bv[8] = {b0.x,b0.y,b0.z,b0.w,b1.x,b1.y,b1.z,b1.w};
#pragma unroll
        for (int i = 0; i < 8; i++)
#pragma unroll
            for (int j = 0; j < 8; j++) accG[i][j] += av[i] * bv[j];
    }
    float al[8], asv[8];
#pragma unroll
    for (int i = 0; i < 8; i++) al[i] = acum[ty*8 + i];
#pragma unroll
    for (int j = 0; j < 8; j++) asv[j] = acum[tx*8 + j];
#pragma unroll
    for (int i = 0; i < 8; i++) {
        int l = ty*8 + i;
#pragma unroll
        for (int j = 0; j < 8; j++) {
            int s = tx*8 + j;
            accG[i][j] = (s <= l) ? accG[i][j] * __expf(al[i] - asv[j]) : 0.f;
        }
        *(float4*)&Ps[l*CTS + tx*8]     = make_float4(accG[i][0],accG[i][1],accG[i][2],accG[i][3]);
        *(float4*)&Ps[l*CTS + tx*8 + 4] = make_float4(accG[i][4],accG[i][5],accG[i][6],accG[i][7]);
    }
    __syncthreads();

    {
        const int lq = tid >> 3, pq = tid & 7;
        float acc[4][4] = {};
        for (int s = 0; s < 128; s++) {
            float bf0 = Xs[s*XSS + pq*4+0];
            float bf1 = Xs[s*XSS + pq*4+1];
            float bf2 = Xs[s*XSS + pq*4+2];
            float bf3 = Xs[s*XSS + pq*4+3];
#pragma unroll
            for (int i = 0; i < 4; i++) {
                float a = Ps[(lq*4+i)*CTS + s];
                acc[i][0] += a*bf0; acc[i][1] += a*bf1;
                acc[i][2] += a*bf2; acc[i][3] += a*bf3;
            }
        }
#pragma unroll
        for (int i = 0; i < 4; i++) {
            size_t row = (bt0 + lq*4 + i) * D_INNER + h*HEADDIM + pq*4;
            *(float4*)&g_y[row] = make_float4(acc[i][0],acc[i][1],acc[i][2],acc[i][3]);
        }
    }

    {
        const int n  = tid >> 2;
        const int pg = tid & 3;
        float acc[8] = {};
        for (int l = 0; l < 128; l++) {
            float bv = Btm[n*CTS + l] * darr[l];
#pragma unroll
            for (int j = 0; j < 8; j++) acc[j] += bv * Xs[l*XSS + pg*8 + j];
        }
        size_t base = (size_t)chunk_id * (HEADDIM * DSTATE);
#pragma unroll
        for (int j = 0; j < 8; j++)
            g_states[base + (size_t)(pg*8 + j) * DSTATE + n] = acc[j];
    }
}

// ---------------------------------------------------------------------------
__global__ void scan_kernel()
{
    const int bh = blockIdx.x;
    const int b = bh >> 5, h = bh & 31;
    const int e = threadIdx.x * 4;
    float4 S = make_float4(0.f,0.f,0.f,0.f);
    for (int c = 0; c < NC_; c++) {
        const int cid = (b * NC_ + c) * NV_ + h;
        size_t base = (size_t)cid * (HEADDIM * DSTATE) + e;
        *(float4*)&g_prevs[base] = S;
        float4 st = *(const float4*)&g_states[base];
        float d = g_dc[cid];
        S.x = S.x*d + st.x; S.y = S.y*d + st.y;
        S.z = S.z*d + st.z; S.w = S.w*d + st.w;
    }
}

// ---------------------------------------------------------------------------
// Y_off + D*x + SiLU gating (R13, conv fused).
// ---------------------------------------------------------------------------
__global__ __launch_bounds__(256) void yoff_kernel(
    const float* __restrict__ cw, const float* __restrict__ cb,
    const float* __restrict__ z_bias, const float* __restrict__ Dvec)
{
    __shared__ float Cs[128 * 65];
    __shared__ float Pv[32 * 65];
    __shared__ float ea[128];
    const int tid = threadIdx.x;
    const int h = blockIdx.x, c = blockIdx.y, b = blockIdx.z;
    const size_t bt0 = (size_t)b * SEQ + (size_t)c * CHUNK_;
    const int chunk_id = (b * NC_ + c) * NV_ + h;
    const float* xb = g_xbcza + (size_t)b * SEQ * IN_PROJ;
    const int tseq0 = c * CHUNK_;

    if (tid < 128) ea[tid] = __expf(g_acum[(size_t)chunk_id * CHUNK_ + tid]);

    {
        const int col = (tid & 15) * 4;
        const int chC = D_INNER + NQK*DSTATE + h*DSTATE + col;
        float wC[4][4];
        load_w4(cw, chC, wC);
        float4 bC = *(const float4*)(cb + chC);
#pragma unroll
        for (int pass = 0; pass < 8; pass++) {
            int r = pass * 16 + (tid >> 4);
            float4 v = conv4(xb, tseq0 + r, chC, wC, bC);
            Cs[r*65 + col+0] = v.x; Cs[r*65 + col+1] = v.y;
            Cs[r*65 + col+2] = v.z; Cs[r*65 + col+3] = v.w;
        }
    }
    size_t pbase = (size_t)chunk_id * (HEADDIM * DSTATE);
#pragma unroll
    for (int pass = 0; pass < 2; pass++) {
        int idx = pass * 256 + tid;
        int p = idx >> 4, col = (idx & 15) * 4;
        float4 v = *(const float4*)(g_prevs + pbase + (size_t)p * DSTATE + col);
        Pv[p*65 + col+0] = v.x; Pv[p*65 + col+1] = v.y;
        Pv[p*65 + col+2] = v.z; Pv[p*65 + col+3] = v.w;
    }
    __syncthreads();

    const int l = tid >> 1;
    const int p0 = (tid & 1) * 16;
    const float e = ea[l];
    float acc[16];
#pragma unroll
    for (int j = 0; j < 16; j++) acc[j] = 0.f;
    for (int n = 0; n < 64; n++) {
        float cv = Cs[l*65 + n];
#pragma unroll
        for (int j = 0; j < 16; j++) acc[j] += cv * Pv[(p0+j)*65 + n];
    }
    const int chbase = h * HEADDIM + p0;
    float xv[16];
    {
        const int tseq = tseq0 + l;
#pragma unroll
        for (int g = 0; g < 4; g++) {
            int ch = chbase + g * 4;
            float wX[4][4];
            load_w4(cw, ch, wX);
            float4 bX = *(const float4*)(cb + ch);
            float4 a = conv4(xb, tseq, ch, wX, bX);
            xv[g*4+0] = a.x; xv[g*4+1] = a.y; xv[g*4+2] = a.z; xv[g*4+3] = a.w;
        }
    }
    const float Dh = Dvec[h];
#pragma unroll
    for (int j = 0; j < 16; j++) {
        int ch = chbase + j;
        size_t oidx = (bt0 + l) * D_INNER + ch;
        float zd = g_xbcza[(bt0 + l) * IN_PROJ + CONV_DIM + ch] + z_bias[ch];
        float sg = zd / (1.f + __expf(-zd));
        g_y[oidx] = (g_y[oidx] + e * acc[j] + Dh * xv[j]) * sg;
    }
}

// ---------------------------------------------------------------------------
extern "C" void kernel_launch(void* const* d_in, const int* in_sizes, int n_in,
                              void* d_out, int out_size)
{
    const float* u      = (const float*)d_in[0];
    const float* W_in   = (const float*)d_in[1];
    const float* conv_w = (const float*)d_in[2];
    const float* conv_b = (const float*)d_in[3];
    const float* z_bias = (const float*)d_in[4];
    const float* Dvec   = (const float*)d_in[5];
    const float* W_out  = (const float*)d_in[6];
    float* out = (float*)d_out;

    float *p_xbcza = nullptr, *p_y = nullptr;
    __half *p_a, *p_w1, *p_w2;
    cudaGetSymbolAddress((void**)&p_xbcza, g_xbcza);
    cudaGetSymbolAddress((void**)&p_y, g_y);
    cudaGetSymbolAddress((void**)&p_a, g_act);
    cudaGetSymbolAddress((void**)&p_w1, g_w1);
    cudaGetSymbolAddress((void**)&p_w2, g_w2);

    static int attr_set = 0;
    if (!attr_set) {
        cudaFuncSetAttribute(gemm_hmma,
            cudaFuncAttributeMaxDynamicSharedMemorySize, GEMM_SMEM);
        size_t csm = (64*CTS + 64*CTS + 128*XSS + 128*CTS + 2*CHUNK_) * sizeof(float);
        cudaFuncSetAttribute(chunk_kernel,
            cudaFuncAttributeMaxDynamicSharedMemorySize, (int)csm);
        attr_set = 1;
    }

    // fp16 conversions
    cvt_f16<<<(BT*1024)/1024, 256>>>(u, p_a, BT*1024, BT*1024);
    cvt_f16<<<(IN_PROJ_PAD*1024)/1024, 256>>>(W_in, p_w1,
                                              IN_PROJ*1024, IN_PROJ_PAD*1024);
    cvt_f16<<<(1024*1024)/1024, 256>>>(W_out, p_w2, 1024*1024, 1024*1024);

    // in-proj
    {
        dim3 grid(IN_PROJ_PAD / 128, BT / 128);
        gemm_hmma<<<grid, 512, GEMM_SMEM>>>(p_a, p_w1,
                                            p_xbcza, D_MODEL, IN_PROJ, IN_PROJ);
    }
    // chunk (conv fused)
    {
        size_t csm = (64*CTS + 64*CTS + 128*XSS + 128*CTS + 2*CHUNK_) * sizeof(float);
        dim3 grid(NV_, NC_, BATCH);
        chunk_kernel<<<grid, 256, csm>>>(conv_w, conv_b);
    }
    scan_kernel<<<BATCH * NV_, 512>>>();
    // y_off (conv fused)
    {
        dim3 grid(NV_, NC_, BATCH);
        yoff_kernel<<<grid, 256>>>(conv_w, conv_b, z_bias, Dvec);
    }
    // out-proj
    cvt_f16<<<(BT*1024)/1024, 256>>>(p_y, p_a, BT*1024, BT*1024);
    {
        dim3 grid(D_MODEL / 128, BT / 128);
        gemm_hmma<<<grid, 512, GEMM_SMEM>>>(p_a, p_w2,
                                            out, D_INNER, D_MODEL, D_MODEL);
    }
}

// round 15
// speedup vs baseline: 2.6373x; 1.0205x over previous
#include <cuda_runtime.h>
#include <cuda_fp16.h>
#include <cstdint>
#include <cstddef>

#define D_MODEL   1024
#define D_INNER   1024
#define NQK       32
#define NV_       32
#define DSTATE    64
#define DCONV     4
#define CHUNK_    128
#define CONV_DIM  5120
#define HEADDIM   32
#define IN_PROJ   6176
#define IN_PROJ_PAD 6272
#define BATCH     2
#define SEQ       8192
#define BT        16384
#define NC_       64

// ---- scratch (device globals) ----
__device__ __align__(16) float g_xbcza[(size_t)BT * IN_PROJ];
__device__ __align__(16) float g_y[(size_t)BT * D_INNER];
__device__ __align__(16) float g_states[(size_t)BATCH * NC_ * NV_ * HEADDIM * DSTATE];
__device__ __align__(16) float g_prevs [(size_t)BATCH * NC_ * NV_ * HEADDIM * DSTATE];
__device__ __align__(16) float g_acum  [(size_t)BATCH * NC_ * NV_ * CHUNK_];
__device__ __align__(16) float g_dc    [BATCH * NC_ * NV_];
__device__ __align__(16) __half g_act[(size_t)BT * 1024];
__device__ __align__(16) __half g_w1 [(size_t)IN_PROJ_PAD * 1024];
__device__ __align__(16) __half g_w2 [(size_t)1024 * 1024];

// ===========================================================================
// fp16 conversion (RN)
// ===========================================================================
__global__ void cvt_f16(const float* __restrict__ s,
                        __half* __restrict__ d,
                        int n_real, int n_total)
{
    int i = (blockIdx.x * 256 + threadIdx.x) * 4;
    if (i >= n_total) return;
    __half h[4];
    if (i < n_real) {
        float4 v = *(const float4*)(s + i);
        h[0] = __float2half_rn(v.x); h[1] = __float2half_rn(v.y);
        h[2] = __float2half_rn(v.z); h[3] = __float2half_rn(v.w);
    } else {
        h[0] = h[1] = h[2] = h[3] = __float2half_rn(0.f);
    }
    *(uint2*)(d + i) = make_uint2(*(uint32_t*)&h[0], *(uint32_t*)&h[2]);
}

// ===========================================================================
// shared helpers
// ===========================================================================
__device__ __forceinline__ uint32_t smem_u32(const void* p) {
    uint32_t a;
    asm("{ .reg .u64 t; cvta.to.shared.u64 t, %1; cvt.u32.u64 %0, t; }"
        : "=r"(a) : "l"(p));
    return a;
}
__device__ __forceinline__ uint32_t sw128(uint32_t off) {
    return off ^ ((off >> 3) & 0x70);
}
__device__ __forceinline__ void ldmat4(uint32_t& r0, uint32_t& r1,
                                       uint32_t& r2, uint32_t& r3, uint32_t a) {
    asm volatile("ldmatrix.sync.aligned.m8n8.x4.shared.b16 {%0,%1,%2,%3}, [%4];"
                 : "=r"(r0), "=r"(r1), "=r"(r2), "=r"(r3) : "r"(a));
}
__device__ __forceinline__ void mma16816h(float* c, const uint32_t* a,
                                          uint32_t b0, uint32_t b1) {
    asm volatile(
        "mma.sync.aligned.m16n8k16.row.col.f32.f16.f16.f32 "
        "{%0,%1,%2,%3}, {%4,%5,%6,%7}, {%8,%9}, {%0,%1,%2,%3};"
        : "+f"(c[0]), "+f"(c[1]), "+f"(c[2]), "+f"(c[3])
        : "r"(a[0]), "r"(a[1]), "r"(a[2]), "r"(a[3]), "r"(b0), "r"(b1));
}
__device__ __forceinline__ void cp16(uint32_t dst, const void* src) {
    asm volatile("cp.async.cg.shared.global [%0], [%1], 16;"
                 :: "r"(dst), "l"(src));
}

// ===========================================================================
// HMMA fp16 GEMM (NT), K-chunk=128 (two 64-col subtiles), 2-stage cp.async,
// 512 threads. Tile layout per operand: 2 subtiles x (128 rows x 128 B, SW128)
// ===========================================================================
__device__ __forceinline__ void load_tile128_async512h(
    const __half* __restrict__ g, int row0, int K, int k0,
    uint32_t sbase, int tid)
{
#pragma unroll
    for (int j = 0; j < 4; j++) {
        int u = tid + 512 * j;          // 2048 16B-units
        int sub = u >> 10;              // 0/1: k-subtile
        int w = u & 1023;
        int row = w >> 3, cg = w & 7;
        uint32_t off = (uint32_t)(sub * 16384 + sw128((uint32_t)(row * 128 + cg * 16)));
        cp16(sbase + off, g + (size_t)(row0 + row) * K + k0 + sub * 64 + cg * 8);
    }
}

#define STAGE_SZ 65536u
#define GEMM_SMEM (2 * 65536)
__global__ __launch_bounds__(512, 1)
void gemm_hmma(const __half* __restrict__ A,
               const __half* __restrict__ B,
               float* __restrict__ C, int K, int Nreal, int ldc)
{
    extern __shared__ char sm[];
    const uint32_t s0 = smem_u32(sm);
    const int tid = threadIdx.x;
    const int wid = tid >> 5, lid = tid & 31;
    const int wm = wid & 3, wn = wid >> 2;
    const int m0 = blockIdx.y * 128, n0 = blockIdx.x * 128;

    float acc[2][4][4];
#pragma unroll
    for (int i = 0; i < 2; i++)
#pragma unroll
        for (int j = 0; j < 4; j++)
#pragma unroll
            for (int q = 0; q < 4; q++) acc[i][j][q] = 0.f;

    const int lrow = lid & 15;
    const int lkb  = (lid >> 4) * 16;
    const int NKC = K >> 7;             // K multiple of 128

    {
        load_tile128_async512h(A, m0, K, 0, s0,         tid);
        load_tile128_async512h(B, n0, K, 0, s0 + 32768, tid);
        asm volatile("cp.async.commit_group;");
    }

    for (int kc = 0; kc < NKC; kc++) {
        if (kc + 1 < NKC) {
            uint32_t base = s0 + ((kc + 1) & 1) * STAGE_SZ;
            int k0 = (kc + 1) << 7;
            load_tile128_async512h(A, m0, K, k0, base,         tid);
            load_tile128_async512h(B, n0, K, k0, base + 32768, tid);
            asm volatile("cp.async.commit_group;");
            asm volatile("cp.async.wait_group 1;");
        } else {
            asm volatile("cp.async.wait_group 0;");
        }
        __syncthreads();

        const uint32_t sA = s0 + (kc & 1) * STAGE_SZ;
        const uint32_t sB = sA + 32768;
#pragma unroll
        for (int ks = 0; ks < 8; ks++) {
            const uint32_t subo = (uint32_t)(ks >> 2) * 16384;
            const int kb = (ks & 3) * 32 + lkb;
            uint32_t bh[2][4];
#pragma unroll
            for (int g2 = 0; g2 < 2; g2++) {
                uint32_t off = sw128((uint32_t)((wn * 32 + g2 * 16 + lrow) * 128 + kb));
                ldmat4(bh[g2][0], bh[g2][1], bh[g2][2], bh[g2][3], sB + subo + off);
            }
#pragma unroll
            for (int mi = 0; mi < 2; mi++) {
                uint32_t ah[4];
                uint32_t off = sw128((uint32_t)((wm * 32 + mi * 16 + lrow) * 128 + kb));
                ldmat4(ah[0], ah[1], ah[2], ah[3], sA + subo + off);
#pragma unroll
                for (int ni = 0; ni < 4; ni++) {
                    const int g2 = ni >> 1, pt = ni & 1;
                    mma16816h(acc[mi][ni], ah, bh[g2][pt], bh[g2][pt + 2]);
                }
            }
        }
        __syncthreads();
    }

    const int crow = lid >> 2, ccol = (lid & 3) * 2;
#pragma unroll
    for (int mi = 0; mi < 2; mi++) {
#pragma unroll
        for (int ni = 0; ni < 4; ni++) {
            int n = n0 + wn * 32 + ni * 8 + ccol;
            if (n >= Nreal) continue;
            int m = m0 + wm * 32 + mi * 16 + crow;
            *(float2*)(C + (size_t)m * ldc + n) =
                make_float2(acc[mi][ni][0], acc[mi][ni][1]);
            *(float2*)(C + (size_t)(m + 8) * ldc + n) =
                make_float2(acc[mi][ni][2], acc[mi][ni][3]);
        }
    }
}

// ---------------------------------------------------------------------------
// Fused conv helper: bias, taps k=0..3 order.
// ---------------------------------------------------------------------------
__device__ __forceinline__ float4 conv4(const float* __restrict__ xb,
                                        int tseq, int ch,
                                        const float w[4][4], float4 bias)
{
    float4 a = bias;
#pragma unroll
    for (int k = 0; k < 4; k++) {
        int tt = tseq - 3 + k;
        if (tt >= 0) {
            float4 v = *(const float4*)(xb + (size_t)tt * IN_PROJ + ch);
            a.x += w[0][k] * v.x; a.y += w[1][k] * v.y;
            a.z += w[2][k] * v.z; a.w += w[3][k] * v.w;
        }
    }
    return a;
}
__device__ __forceinline__ void load_w4(const float* __restrict__ cw, int ch,
                                        float w[4][4])
{
#pragma unroll
    for (int i = 0; i < 4; i++)
#pragma unroll
        for (int k = 0; k < 4; k++) w[i][k] = cw[(ch + i) * 4 + k];
}

// ---------------------------------------------------------------------------
// Chunk kernel (conv fused). per (h, c, b). 153,088 B smem.
// ---------------------------------------------------------------------------
#define CTS 132
#define XSS 33
__global__ __launch_bounds__(256, 1) void chunk_kernel(
    const float* __restrict__ cw, const float* __restrict__ cb)
{
    extern __shared__ float smf[];
    float* Ct   = smf;
    float* Btm  = Ct + 64 * CTS;
    float* Xs   = Btm + 64 * CTS;
    float* Ps   = Xs + 128 * XSS;
    float* acum = Ps + 128 * CTS;
    float* darr = acum + CHUNK_;

    const int tid = threadIdx.x;
    const int h = blockIdx.x, c = blockIdx.y, b = blockIdx.z;
    const size_t bt0 = (size_t)b * SEQ + (size_t)c * CHUNK_;
    const int chunk_id = (b * NC_ + c) * NV_ + h;
    const float* xb = g_xbcza + (size_t)b * SEQ * IN_PROJ;
    const int tseq0 = c * CHUNK_;

    if (tid < 128) {
        float a = g_xbcza[(bt0 + tid) * IN_PROJ + (CONV_DIM + D_INNER) + h];
        darr[tid] = (a > 20.f) ? a : log1pf(expf(a));
    }
    __syncthreads();
    if (tid < 32) {
        float v0 = darr[tid*4+0], v1 = darr[tid*4+1];
        float v2 = darr[tid*4+2], v3 = darr[tid*4+3];
        float s1 = v0+v1, s2 = s1+v2, s3 = s2+v3;
        float t = s3;
#pragma unroll
        for (int o = 1; o < 32; o <<= 1) {
            float u2 = __shfl_up_sync(0xffffffffu, t, o);
            if (tid >= o) t += u2;
        }
        float base = t - s3;
        acum[tid*4+0] = -(base+v0); acum[tid*4+1] = -(base+s1);
        acum[tid*4+2] = -(base+s2); acum[tid*4+3] = -(base+s3);
    }
    __syncthreads();
    const float alast = acum[127];
    if (tid < 128) {
        darr[tid] = __expf(alast - acum[tid]);
        g_acum[(size_t)chunk_id * CHUNK_ + tid] = acum[tid];
    }
    if (tid == 0) g_dc[chunk_id] = __expf(alast);

    {
        const int col = (tid & 15) * 4;
        const int chC = D_INNER + NQK*DSTATE + h*DSTATE + col;
        const int chB = D_INNER + h*DSTATE + col;
        float wC[4][4], wB[4][4];
        load_w4(cw, chC, wC);
        load_w4(cw, chB, wB);
        float4 bC = *(const float4*)(cb + chC);
        float4 bB = *(const float4*)(cb + chB);
#pragma unroll
        for (int pass = 0; pass < 8; pass++) {
            int r = pass * 16 + (tid >> 4);
            float4 aC = conv4(xb, tseq0 + r, chC, wC, bC);
            float4 aB = conv4(xb, tseq0 + r, chB, wB, bB);
            Ct[(col+0)*CTS + r] = aC.x; Ct[(col+1)*CTS + r] = aC.y;
            Ct[(col+2)*CTS + r] = aC.z; Ct[(col+3)*CTS + r] = aC.w;
            Btm[(col+0)*CTS + r] = aB.x; Btm[(col+1)*CTS + r] = aB.y;
            Btm[(col+2)*CTS + r] = aB.z; Btm[(col+3)*CTS + r] = aB.w;
        }
    }
    {
        const int col = (tid & 7) * 4;
        const int chX = h*HEADDIM + col;
        float wX[4][4];
        load_w4(cw, chX, wX);
        float4 bX = *(const float4*)(cb + chX);
#pragma unroll
        for (int pass = 0; pass < 4; pass++) {
            int r = pass * 32 + (tid >> 3);
            float4 aX = conv4(xb, tseq0 + r, chX, wX, bX);
            Xs[r*XSS + col+0] = aX.x; Xs[r*XSS + col+1] = aX.y;
            Xs[r*XSS + col+2] = aX.z; Xs[r*XSS + col+3] = aX.w;
        }
    }
    __syncthreads();

    const int ty = tid >> 4, tx = tid & 15;
    float accG[8][8];
#pragma unroll
    for (int i = 0; i < 8; i++)
#pragma unroll
        for (int j = 0; j < 8; j++) accG[i][j] = 0.f;
#pragma unroll 4
    for (int n = 0; n < 64; n++) {
        float4 a0 = *(const float4*)&Ct[n*CTS + ty*8];
        float4 a1 = *(const float4*)&Ct[n*CTS + ty*8 + 4];
        float4 b0 = *(const float4*)&Btm[n*CTS + tx*8];
        float4 b1 = *(const float4*)&Btm[n*CTS + tx*8 + 4];
        float av[8] = {a0.x,a0.y,a0.z,a0.w,a1.x,a1.y,a1.z,a1.w};
        float bv[8] = {b0.x,b0.y,b0.z,b0.w,b1.x,b1.y,b1.z,b1.w};
#pragma unroll
        for (int i = 0; i < 8; i++)
#pragma unroll
            for (int j = 0; j < 8; j++) accG[i][j] += av[i] * bv[j];
    }
    float al[8], asv[8];
#pragma unroll
    for (int i = 0; i < 8; i++) al[i] = acum[ty*8 + i];
#pragma unroll
    for (int j = 0; j < 8; j++) asv[j] = acum[tx*8 + j];
#pragma unroll
    for (int i = 0; i < 8; i++) {
        int l = ty*8 + i;
#pragma unroll
        for (int j = 0; j < 8; j++) {
            int s = tx*8 + j;
            accG[i][j] = (s <= l) ? accG[i][j] * __expf(al[i] - asv[j]) : 0.f;
        }
        *(float4*)&Ps[l*CTS + tx*8]     = make_float4(accG[i][0],accG[i][1],accG[i][2],accG[i][3]);
        *(float4*)&Ps[l*CTS + tx*8 + 4] = make_float4(accG[i][4],accG[i][5],accG[i][6],accG[i][7]);
    }
    __syncthreads();

    {
        const int lq = tid >> 3, pq = tid & 7;
        float acc[4][4] = {};
        for (int s = 0; s < 128; s++) {
            float bf0 = Xs[s*XSS + pq*4+0];
            float bf1 = Xs[s*XSS + pq*4+1];
            float bf2 = Xs[s*XSS + pq*4+2];
            float bf3 = Xs[s*XSS + pq*4+3];
#pragma unroll
            for (int i = 0; i < 4; i++) {
                float a = Ps[(lq*4+i)*CTS + s];
                acc[i][0] += a*bf0; acc[i][1] += a*bf1;
                acc[i][2] += a*bf2; acc[i][3] += a*bf3;
            }
        }
#pragma unroll
        for (int i = 0; i < 4; i++) {
            size_t row = (bt0 + lq*4 + i) * D_INNER + h*HEADDIM + pq*4;
            *(float4*)&g_y[row] = make_float4(acc[i][0],acc[i][1],acc[i][2],acc[i][3]);
        }
    }

    {
        const int n  = tid >> 2;
        const int pg = tid & 3;
        float acc[8] = {};
        for (int l = 0; l < 128; l++) {
            float bv = Btm[n*CTS + l] * darr[l];
#pragma unroll
            for (int j = 0; j < 8; j++) acc[j] += bv * Xs[l*XSS + pg*8 + j];
        }
        size_t base = (size_t)chunk_id * (HEADDIM * DSTATE);
#pragma unroll
        for (int j = 0; j < 8; j++)
            g_states[base + (size_t)(pg*8 + j) * DSTATE + n] = acc[j];
    }
}

// ---------------------------------------------------------------------------
__global__ void scan_kernel()
{
    const int bh = blockIdx.x;
    const int b = bh >> 5, h = bh & 31;
    const int e = threadIdx.x * 4;
    float4 S = make_float4(0.f,0.f,0.f,0.f);
    for (int c = 0; c < NC_; c++) {
        const int cid = (b * NC_ + c) * NV_ + h;
        size_t base = (size_t)cid * (HEADDIM * DSTATE) + e;
        *(float4*)&g_prevs[base] = S;
        float4 st = *(const float4*)&g_states[base];
        float d = g_dc[cid];
        S.x = S.x*d + st.x; S.y = S.y*d + st.y;
        S.z = S.z*d + st.z; S.w = S.w*d + st.w;
    }
}

// ---------------------------------------------------------------------------
// Y_off + D*x + SiLU gating (conv fused); writes fp16 y directly for out-proj.
// ---------------------------------------------------------------------------
__global__ __launch_bounds__(256) void yoff_kernel(
    const float* __restrict__ cw, const float* __restrict__ cb,
    const float* __restrict__ z_bias, const float* __restrict__ Dvec,
    __half* __restrict__ yh)
{
    __shared__ float Cs[128 * 65];
    __shared__ float Pv[32 * 65];
    __shared__ float ea[128];
    const int tid = threadIdx.x;
    const int h = blockIdx.x, c = blockIdx.y, b = blockIdx.z;
    const size_t bt0 = (size_t)b * SEQ + (size_t)c * CHUNK_;
    const int chunk_id = (b * NC_ + c) * NV_ + h;
    const float* xb = g_xbcza + (size_t)b * SEQ * IN_PROJ;
    const int tseq0 = c * CHUNK_;

    if (tid < 128) ea[tid] = __expf(g_acum[(size_t)chunk_id * CHUNK_ + tid]);

    {
        const int col = (tid & 15) * 4;
        const int chC = D_INNER + NQK*DSTATE + h*DSTATE + col;
        float wC[4][4];
        load_w4(cw, chC, wC);
        float4 bC = *(const float4*)(cb + chC);
#pragma unroll
        for (int pass = 0; pass < 8; pass++) {
            int r = pass * 16 + (tid >> 4);
            float4 v = conv4(xb, tseq0 + r, chC, wC, bC);
            Cs[r*65 + col+0] = v.x; Cs[r*65 + col+1] = v.y;
            Cs[r*65 + col+2] = v.z; Cs[r*65 + col+3] = v.w;
        }
    }
    size_t pbase = (size_t)chunk_id * (HEADDIM * DSTATE);
#pragma unroll
    for (int pass = 0; pass < 2; pass++) {
        int idx = pass * 256 + tid;
        int p = idx >> 4, col = (idx & 15) * 4;
        float4 v = *(const float4*)(g_prevs + pbase + (size_t)p * DSTATE + col);
        Pv[p*65 + col+0] = v.x; Pv[p*65 + col+1] = v.y;
        Pv[p*65 + col+2] = v.z; Pv[p*65 + col+3] = v.w;
    }
    __syncthreads();

    const int l = tid >> 1;
    const int p0 = (tid & 1) * 16;
    const float e = ea[l];
    float acc[16];
#pragma unroll
    for (int j = 0; j < 16; j++) acc[j] = 0.f;
    for (int n = 0; n < 64; n++) {
        float cv = Cs[l*65 + n];
#pragma unroll
        for (int j = 0; j < 16; j++) acc[j] += cv * Pv[(p0+j)*65 + n];
    }
    const int chbase = h * HEADDIM + p0;
    float xv[16];
    {
        const int tseq = tseq0 + l;
#pragma unroll
        for (int g = 0; g < 4; g++) {
            int ch = chbase + g * 4;
            float wX[4][4];
            load_w4(cw, ch, wX);
            float4 bX = *(const float4*)(cb + ch);
            float4 a = conv4(xb, tseq, ch, wX, bX);
            xv[g*4+0] = a.x; xv[g*4+1] = a.y; xv[g*4+2] = a.z; xv[g*4+3] = a.w;
        }
    }
    const float Dh = Dvec[h];
    __half hv[16];
#pragma unroll
    for (int j = 0; j < 16; j++) {
        int ch = chbase + j;
        size_t oidx = (bt0 + l) * D_INNER + ch;
        float zd = g_xbcza[(bt0 + l) * IN_PROJ + CONV_DIM + ch] + z_bias[ch];
        float sg = zd / (1.f + __expf(-zd));
        hv[j] = __float2half_rn((g_y[oidx] + e * acc[j] + Dh * xv[j]) * sg);
    }
    size_t ob = (bt0 + l) * (size_t)D_INNER + chbase;
#pragma unroll
    for (int q = 0; q < 2; q++)
        *(uint4*)(yh + ob + q * 8) = make_uint4(
            *(uint32_t*)&hv[q*8+0], *(uint32_t*)&hv[q*8+2],
            *(uint32_t*)&hv[q*8+4], *(uint32_t*)&hv[q*8+6]);
}

// ---------------------------------------------------------------------------
extern "C" void kernel_launch(void* const* d_in, const int* in_sizes, int n_in,
                              void* d_out, int out_size)
{
    const float* u      = (const float*)d_in[0];
    const float* W_in   = (const float*)d_in[1];
    const float* conv_w = (const float*)d_in[2];
    const float* conv_b = (const float*)d_in[3];
    const float* z_bias = (const float*)d_in[4];
    const float* Dvec   = (const float*)d_in[5];
    const float* W_out  = (const float*)d_in[6];
    float* out = (float*)d_out;

    float *p_xbcza = nullptr;
    __half *p_a, *p_w1, *p_w2;
    cudaGetSymbolAddress((void**)&p_xbcza, g_xbcza);
    cudaGetSymbolAddress((void**)&p_a, g_act);
    cudaGetSymbolAddress((void**)&p_w1, g_w1);
    cudaGetSymbolAddress((void**)&p_w2, g_w2);

    static int attr_set = 0;
    if (!attr_set) {
        cudaFuncSetAttribute(gemm_hmma,
            cudaFuncAttributeMaxDynamicSharedMemorySize, GEMM_SMEM);
        size_t csm = (64*CTS + 64*CTS + 128*XSS + 128*CTS + 2*CHUNK_) * sizeof(float);
        cudaFuncSetAttribute(chunk_kernel,
            cudaFuncAttributeMaxDynamicSharedMemorySize, (int)csm);
        attr_set = 1;
    }

    // fp16 conversions
    cvt_f16<<<(BT*1024)/1024, 256>>>(u, p_a, BT*1024, BT*1024);
    cvt_f16<<<(IN_PROJ_PAD*1024)/1024, 256>>>(W_in, p_w1,
                                              IN_PROJ*1024, IN_PROJ_PAD*1024);
    cvt_f16<<<(1024*1024)/1024, 256>>>(W_out, p_w2, 1024*1024, 1024*1024);

    // in-proj
    {
        dim3 grid(IN_PROJ_PAD / 128, BT / 128);
        gemm_hmma<<<grid, 512, GEMM_SMEM>>>(p_a, p_w1,
                                            p_xbcza, D_MODEL, IN_PROJ, IN_PROJ);
    }
    // chunk (conv fused)
    {
        size_t csm = (64*CTS + 64*CTS + 128*XSS + 128*CTS + 2*CHUNK_) * sizeof(float);
        dim3 grid(NV_, NC_, BATCH);
        chunk_kernel<<<grid, 256, csm>>>(conv_w, conv_b);
    }
    scan_kernel<<<BATCH * NV_, 512>>>();
    // y_off (conv fused, fp16 output)
    {
        dim3 grid(NV_, NC_, BATCH);
        yoff_kernel<<<grid, 256>>>(conv_w, conv_b, z_bias, Dvec, p_a);
    }
    // out-proj (consumes yoff's fp16 output directly)
    {
        dim3 grid(D_MODEL / 128, BT / 128);
        gemm_hmma<<<grid, 512, GEMM_SMEM>>>(p_a, p_w2,
                                            out, D_INNER, D_MODEL, D_MODEL);
    }
}

// round 16
// speedup vs baseline: 2.7681x; 1.0496x over previous
#include <cuda_runtime.h>
#include <cuda_fp16.h>
#include <cstdint>
#include <cstddef>

#define D_MODEL   1024
#define D_INNER   1024
#define NQK       32
#define NV_       32
#define DSTATE    64
#define DCONV     4
#define CHUNK_    128
#define CONV_DIM  5120
#define HEADDIM   32
#define IN_PROJ   6176
#define IN_PROJ_PAD 6272
#define BATCH     2
#define SEQ       8192
#define BT        16384
#define NC_       64

// ---- scratch (device globals) ----
__device__ __align__(16) float g_xbcza[(size_t)BT * IN_PROJ];
__device__ __align__(16) float g_y[(size_t)BT * D_INNER];
__device__ __align__(16) float g_states[(size_t)BATCH * NC_ * NV_ * HEADDIM * DSTATE];
__device__ __align__(16) float g_prevs [(size_t)BATCH * NC_ * NV_ * HEADDIM * DSTATE];
__device__ __align__(16) float g_acum  [(size_t)BATCH * NC_ * NV_ * CHUNK_];
__device__ __align__(16) float g_dc    [BATCH * NC_ * NV_];
__device__ __align__(16) __half g_act[(size_t)BT * 1024];
__device__ __align__(16) __half g_w1 [(size_t)IN_PROJ_PAD * 1024];
__device__ __align__(16) __half g_w2 [(size_t)1024 * 1024];

// ===========================================================================
// fp16 conversion (RN)
// ===========================================================================
__global__ void cvt_f16(const float* __restrict__ s,
                        __half* __restrict__ d,
                        int n_real, int n_total)
{
    int i = (blockIdx.x * 256 + threadIdx.x) * 4;
    if (i >= n_total) return;
    __half h[4];
    if (i < n_real) {
        float4 v = *(const float4*)(s + i);
        h[0] = __float2half_rn(v.x); h[1] = __float2half_rn(v.y);
        h[2] = __float2half_rn(v.z); h[3] = __float2half_rn(v.w);
    } else {
        h[0] = h[1] = h[2] = h[3] = __float2half_rn(0.f);
    }
    *(uint2*)(d + i) = make_uint2(*(uint32_t*)&h[0], *(uint32_t*)&h[2]);
}

// ===========================================================================
// shared helpers
// ===========================================================================
__device__ __forceinline__ uint32_t smem_u32(const void* p) {
    uint32_t a;
    asm("{ .reg .u64 t; cvta.to.shared.u64 t, %1; cvt.u32.u64 %0, t; }"
        : "=r"(a) : "l"(p));
    return a;
}
__device__ __forceinline__ uint32_t sw128(uint32_t off) {
    return off ^ ((off >> 3) & 0x70);
}
__device__ __forceinline__ void ldmat4(uint32_t& r0, uint32_t& r1,
                                       uint32_t& r2, uint32_t& r3, uint32_t a) {
    asm volatile("ldmatrix.sync.aligned.m8n8.x4.shared.b16 {%0,%1,%2,%3}, [%4];"
                 : "=r"(r0), "=r"(r1), "=r"(r2), "=r"(r3) : "r"(a));
}
__device__ __forceinline__ void mma16816h(float* c, const uint32_t* a,
                                          uint32_t b0, uint32_t b1) {
    asm volatile(
        "mma.sync.aligned.m16n8k16.row.col.f32.f16.f16.f32 "
        "{%0,%1,%2,%3}, {%4,%5,%6,%7}, {%8,%9}, {%0,%1,%2,%3};"
        : "+f"(c[0]), "+f"(c[1]), "+f"(c[2]), "+f"(c[3])
        : "r"(a[0]), "r"(a[1]), "r"(a[2]), "r"(a[3]), "r"(b0), "r"(b1));
}
__device__ __forceinline__ void cp16(uint32_t dst, const void* src) {
    asm volatile("cp.async.cg.shared.global [%0], [%1], 16;"
                 :: "r"(dst), "l"(src));
}

// ===========================================================================
// HMMA fp16 single-pass GEMM (NT), K-chunk=64, 2-stage cp.async, 256 threads,
// 2 CTAs/SM. 8 warps in 2x4; warp tile 64x32 (A 4 LDSM + B 2 LDSM : 16 MMA).
// ===========================================================================
__device__ __forceinline__ void load_tile_async256h(
    const __half* __restrict__ g, int row0, int K, int k0,
    uint32_t sbase, int tid)
{
#pragma unroll
    for (int j = 0; j < 4; j++) {
        int u = tid + 256 * j;          // 1024 16B-units: 128 rows x 8 groups
        int row = u >> 3, cg = u & 7;
        uint32_t off = (uint32_t)(row * 128 + cg * 16);
        cp16(sbase + sw128(off), g + (size_t)(row0 + row) * K + k0 + cg * 8);
    }
}

#define STAGE_SZ 32768u
#define GEMM_SMEM (2 * 32768)
__global__ __launch_bounds__(256, 2)
void gemm_hmma(const __half* __restrict__ A,
               const __half* __restrict__ B,
               float* __restrict__ C, int K, int Nreal, int ldc)
{
    extern __shared__ char sm[];
    const uint32_t s0 = smem_u32(sm);
    const int tid = threadIdx.x;
    const int wid = tid >> 5, lid = tid & 31;
    const int wm = wid & 1, wn = wid >> 1;      // 2 x 4 warp grid, 64x32 tiles
    const int m0 = blockIdx.y * 128, n0 = blockIdx.x * 128;

    float acc[4][4][4];
#pragma unroll
    for (int i = 0; i < 4; i++)
#pragma unroll
        for (int j = 0; j < 4; j++)
#pragma unroll
            for (int q = 0; q < 4; q++) acc[i][j][q] = 0.f;

    const int lrow = lid & 15;
    const int lkb  = (lid >> 4) * 16;
    const int NKC = K >> 6;

    {
        load_tile_async256h(A, m0, K, 0, s0,         tid);
        load_tile_async256h(B, n0, K, 0, s0 + 16384, tid);
        asm volatile("cp.async.commit_group;");
    }

    for (int kc = 0; kc < NKC; kc++) {
        if (kc + 1 < NKC) {
            uint32_t base = s0 + ((kc + 1) & 1) * STAGE_SZ;
            int k0 = (kc + 1) << 6;
            load_tile_async256h(A, m0, K, k0, base,         tid);
            load_tile_async256h(B, n0, K, k0, base + 16384, tid);
            asm volatile("cp.async.commit_group;");
            asm volatile("cp.async.wait_group 1;");
        } else {
            asm volatile("cp.async.wait_group 0;");
        }
        __syncthreads();

        const uint32_t sA = s0 + (kc & 1) * STAGE_SZ;
        const uint32_t sB = sA + 16384;
#pragma unroll
        for (int ks = 0; ks < 4; ks++) {
            const int kb = ks * 32 + lkb;
            uint32_t bh[2][4];
#pragma unroll
            for (int g2 = 0; g2 < 2; g2++) {
                uint32_t off = sw128((uint32_t)((wn * 32 + g2 * 16 + lrow) * 128 + kb));
                ldmat4(bh[g2][0], bh[g2][1], bh[g2][2], bh[g2][3], sB + off);
            }
#pragma unroll
            for (int mi = 0; mi < 4; mi++) {
                uint32_t ah[4];
                uint32_t off = sw128((uint32_t)((wm * 64 + mi * 16 + lrow) * 128 + kb));
                ldmat4(ah[0], ah[1], ah[2], ah[3], sA + off);
#pragma unroll
                for (int ni = 0; ni < 4; ni++) {
                    const int g2 = ni >> 1, pt = ni & 1;
                    mma16816h(acc[mi][ni], ah, bh[g2][pt], bh[g2][pt + 2]);
                }
            }
        }
        __syncthreads();
    }

    const int crow = lid >> 2, ccol = (lid & 3) * 2;
#pragma unroll
    for (int mi = 0; mi < 4; mi++) {
#pragma unroll
        for (int ni = 0; ni < 4; ni++) {
            int n = n0 + wn * 32 + ni * 8 + ccol;
            if (n >= Nreal) continue;
            int m = m0 + wm * 64 + mi * 16 + crow;
            *(float2*)(C + (size_t)m * ldc + n) =
                make_float2(acc[mi][ni][0], acc[mi][ni][1]);
            *(float2*)(C + (size_t)(m + 8) * ldc + n) =
                make_float2(acc[mi][ni][2], acc[mi][ni][3]);
        }
    }
}

// ---------------------------------------------------------------------------
// Fused conv helper: bias, taps k=0..3 order.
// ---------------------------------------------------------------------------
__device__ __forceinline__ float4 conv4(const float* __restrict__ xb,
                                        int tseq, int ch,
                                        const float w[4][4], float4 bias)
{
    float4 a = bias;
#pragma unroll
    for (int k = 0; k < 4; k++) {
        int tt = tseq - 3 + k;
        if (tt >= 0) {
            float4 v = *(const float4*)(xb + (size_t)tt * IN_PROJ + ch);
            a.x += w[0][k] * v.x; a.y += w[1][k] * v.y;
            a.z += w[2][k] * v.z; a.w += w[3][k] * v.w;
        }
    }
    return a;
}
__device__ __forceinline__ void load_w4(const float* __restrict__ cw, int ch,
                                        float w[4][4])
{
#pragma unroll
    for (int i = 0; i < 4; i++)
#pragma unroll
        for (int k = 0; k < 4; k++) w[i][k] = cw[(ch + i) * 4 + k];
}

// ---------------------------------------------------------------------------
// Chunk kernel (conv fused). per (h, c, b). 153,088 B smem.
// ---------------------------------------------------------------------------
#define CTS 132
#define XSS 33
__global__ __launch_bounds__(256, 1) void chunk_kernel(
    const float* __restrict__ cw, const float* __restrict__ cb)
{
    extern __shared__ float smf[];
    float* Ct   = smf;
    float* Btm  = Ct + 64 * CTS;
    float* Xs   = Btm + 64 * CTS;
    float* Ps   = Xs + 128 * XSS;
    float* acum = Ps + 128 * CTS;
    float* darr = acum + CHUNK_;

    const int tid = threadIdx.x;
    const int h = blockIdx.x, c = blockIdx.y, b = blockIdx.z;
    const size_t bt0 = (size_t)b * SEQ + (size_t)c * CHUNK_;
    const int chunk_id = (b * NC_ + c) * NV_ + h;
    const float* xb = g_xbcza + (size_t)b * SEQ * IN_PROJ;
    const int tseq0 = c * CHUNK_;

    if (tid < 128) {
        float a = g_xbcza[(bt0 + tid) * IN_PROJ + (CONV_DIM + D_INNER) + h];
        darr[tid] = (a > 20.f) ? a : log1pf(expf(a));
    }
    __syncthreads();
    if (tid < 32) {
        float v0 = darr[tid*4+0], v1 = darr[tid*4+1];
        float v2 = darr[tid*4+2], v3 = darr[tid*4+3];
        float s1 = v0+v1, s2 = s1+v2, s3 = s2+v3;
        float t = s3;
#pragma unroll
        for (int o = 1; o < 32; o <<= 1) {
            float u2 = __shfl_up_sync(0xffffffffu, t, o);
            if (tid >= o) t += u2;
        }
        float base = t - s3;
        acum[tid*4+0] = -(base+v0); acum[tid*4+1] = -(base+s1);
        acum[tid*4+2] = -(base+s2); acum[tid*4+3] = -(base+s3);
    }
    __syncthreads();
    const float alast = acum[127];
    if (tid < 128) {
        darr[tid] = __expf(alast - acum[tid]);
        g_acum[(size_t)chunk_id * CHUNK_ + tid] = acum[tid];
    }
    if (tid == 0) g_dc[chunk_id] = __expf(alast);

    {
        const int col = (tid & 15) * 4;
        const int chC = D_INNER + NQK*DSTATE + h*DSTATE + col;
        const int chB = D_INNER + h*DSTATE + col;
        float wC[4][4], wB[4][4];
        load_w4(cw, chC, wC);
        load_w4(cw, chB, wB);
        float4 bC = *(const float4*)(cb + chC);
        float4 bB = *(const float4*)(cb + chB);
#pragma unroll
        for (int pass = 0; pass < 8; pass++) {
            int r = pass * 16 + (tid >> 4);
            float4 aC = conv4(xb, tseq0 + r, chC, wC, bC);
            float4 aB = conv4(xb, tseq0 + r, chB, wB, bB);
            Ct[(col+0)*CTS + r] = aC.x; Ct[(col+1)*CTS + r] = aC.y;
            Ct[(col+2)*CTS + r] = aC.z; Ct[(col+3)*CTS + r] = aC.w;
            Btm[(col+0)*CTS + r] = aB.x; Btm[(col+1)*CTS + r] = aB.y;
            Btm[(col+2)*CTS + r] = aB.z; Btm[(col+3)*CTS + r] = aB.w;
        }
    }
    {
        const int col = (tid & 7) * 4;
        const int chX = h*HEADDIM + col;
        float wX[4][4];
        load_w4(cw, chX, wX);
        float4 bX = *(const float4*)(cb + chX);
#pragma unroll
        for (int pass = 0; pass < 4; pass++) {
            int r = pass * 32 + (tid >> 3);
            float4 aX = conv4(xb, tseq0 + r, chX, wX, bX);
            Xs[r*XSS + col+0] = aX.x; Xs[r*XSS + col+1] = aX.y;
            Xs[r*XSS + col+2] = aX.z; Xs[r*XSS + col+3] = aX.w;
        }
    }
    __syncthreads();

    const int ty = tid >> 4, tx = tid & 15;
    float accG[8][8];
#pragma unroll
    for (int i = 0; i < 8; i++)
#pragma unroll
        for (int j = 0; j < 8; j++) accG[i][j] = 0.f;
#pragma unroll 4
    for (int n = 0; n < 64; n++) {
        float4 a0 = *(const float4*)&Ct[n*CTS + ty*8];
        float4 a1 = *(const float4*)&Ct[n*CTS + ty*8 + 4];
        float4 b0 = *(const float4*)&Btm[n*CTS + tx*8];
        float4 b1 = *(const float4*)&Btm[n*CTS + tx*8 + 4];
        float av[8] = {a0.x,a0.y,a0.z,a0.w,a1.x,a1.y,a1.z,a1.w};
        float bv[8] = {b0.x,b0.y,b0.z,b0.w,b1.x,b1.y,b1.z,b1.w};
#pragma unroll
        for (int i = 0; i < 8; i++)
#pragma unroll
            for (int j = 0; j < 8; j++) accG[i][j] += av[i] * bv[j];
    }
    float al[8], asv[8];
#pragma unroll
    for (int i = 0; i < 8; i++) al[i] = acum[ty*8 + i];
#pragma unroll
    for (int j = 0; j < 8; j++) asv[j] = acum[tx*8 + j];
#pragma unroll
    for (int i = 0; i < 8; i++) {
        int l = ty*8 + i;
#pragma unroll
        for (int j = 0; j < 8; j++) {
            int s = tx*8 + j;
            accG[i][j] = (s <= l) ? accG[i][j] * __expf(al[i] - asv[j]) : 0.f;
        }
        *(float4*)&Ps[l*CTS + tx*8]     = make_float4(accG[i][0],accG[i][1],accG[i][2],accG[i][3]);
        *(float4*)&Ps[l*CTS + tx*8 + 4] = make_float4(accG[i][4],accG[i][5],accG[i][6],accG[i][7]);
    }
    __syncthreads();

    {
        const int lq = tid >> 3, pq = tid & 7;
        float acc[4][4] = {};
        for (int s = 0; s < 128; s++) {
            float bf0 = Xs[s*XSS + pq*4+0];
            float bf1 = Xs[s*XSS + pq*4+1];
            float bf2 = Xs[s*XSS + pq*4+2];
            float bf3 = Xs[s*XSS + pq*4+3];
#pragma unroll
            for (int i = 0; i < 4; i++) {
                float a = Ps[(lq*4+i)*CTS + s];
                acc[i][0] += a*bf0; acc[i][1] += a*bf1;
                acc[i][2] += a*bf2; acc[i][3] += a*bf3;
            }
        }
#pragma unroll
        for (int i = 0; i < 4; i++) {
            size_t row = (bt0 + lq*4 + i) * D_INNER + h*HEADDIM + pq*4;
            *(float4*)&g_y[row] = make_float4(acc[i][0],acc[i][1],acc[i][2],acc[i][3]);
        }
    }

    {
        const int n  = tid >> 2;
        const int pg = tid & 3;
        float acc[8] = {};
        for (int l = 0; l < 128; l++) {
            float bv = Btm[n*CTS + l] * darr[l];
#pragma unroll
            for (int j = 0; j < 8; j++) acc[j] += bv * Xs[l*XSS + pg*8 + j];
        }
        size_t base = (size_t)chunk_id * (HEADDIM * DSTATE);
#pragma unroll
        for (int j = 0; j < 8; j++)
            g_states[base + (size_t)(pg*8 + j) * DSTATE + n] = acc[j];
    }
}

// ---------------------------------------------------------------------------
__global__ void scan_kernel()
{
    const int bh = blockIdx.x;
    const int b = bh >> 5, h = bh & 31;
    const int e = threadIdx.x * 4;
    float4 S = make_float4(0.f,0.f,0.f,0.f);
    for (int c = 0; c < NC_; c++) {
        const int cid = (b * NC_ + c) * NV_ + h;
        size_t base = (size_t)cid * (HEADDIM * DSTATE) + e;
        *(float4*)&g_prevs[base] = S;
        float4 st = *(const float4*)&g_states[base];
        float d = g_dc[cid];
        S.x = S.x*d + st.x; S.y = S.y*d + st.y;
        S.z = S.z*d + st.z; S.w = S.w*d + st.w;
    }
}

// ---------------------------------------------------------------------------
// Y_off + D*x + SiLU gating (conv fused); writes fp16 y directly for out-proj.
// ---------------------------------------------------------------------------
__global__ __launch_bounds__(256) void yoff_kernel(
    const float* __restrict__ cw, const float* __restrict__ cb,
    const float* __restrict__ z_bias, const float* __restrict__ Dvec,
    __half* __restrict__ yh)
{
    __shared__ float Cs[128 * 65];
    __shared__ float Pv[32 * 65];
    __shared__ float ea[128];
    const int tid = threadIdx.x;
    const int h = blockIdx.x, c = blockIdx.y, b = blockIdx.z;
    const size_t bt0 = (size_t)b * SEQ + (size_t)c * CHUNK_;
    const int chunk_id = (b * NC_ + c) * NV_ + h;
    const float* xb = g_xbcza + (size_t)b * SEQ * IN_PROJ;
    const int tseq0 = c * CHUNK_;

    if (tid < 128) ea[tid] = __expf(g_acum[(size_t)chunk_id * CHUNK_ + tid]);

    {
        const int col = (tid & 15) * 4;
        const int chC = D_INNER + NQK*DSTATE + h*DSTATE + col;
        float wC[4][4];
        load_w4(cw, chC, wC);
        float4 bC = *(const float4*)(cb + chC);
#pragma unroll
        for (int pass = 0; pass < 8; pass++) {
            int r = pass * 16 + (tid >> 4);
            float4 v = conv4(xb, tseq0 + r, chC, wC, bC);
            Cs[r*65 + col+0] = v.x; Cs[r*65 + col+1] = v.y;
            Cs[r*65 + col+2] = v.z; Cs[r*65 + col+3] = v.w;
        }
    }
    size_t pbase = (size_t)chunk_id * (HEADDIM * DSTATE);
#pragma unroll
    for (int pass = 0; pass < 2; pass++) {
        int idx = pass * 256 + tid;
        int p = idx >> 4, col = (idx & 15) * 4;
        float4 v = *(const float4*)(g_prevs + pbase + (size_t)p * DSTATE + col);
        Pv[p*65 + col+0] = v.x; Pv[p*65 + col+1] = v.y;
        Pv[p*65 + col+2] = v.z; Pv[p*65 + col+3] = v.w;
    }
    __syncthreads();

    const int l = tid >> 1;
    const int p0 = (tid & 1) * 16;
    const float e = ea[l];
    float acc[16];
#pragma unroll
    for (int j = 0; j < 16; j++) acc[j] = 0.f;
    for (int n = 0; n < 64; n++) {
        float cv = Cs[l*65 + n];
#pragma unroll
        for (int j = 0; j < 16; j++) acc[j] += cv * Pv[(p0+j)*65 + n];
    }
    const int chbase = h * HEADDIM + p0;
    float xv[16];
    {
        const int tseq = tseq0 + l;
#pragma unroll
        for (int g = 0; g < 4; g++) {
            int ch = chbase + g * 4;
            float wX[4][4];
            load_w4(cw, ch, wX);
            float4 bX = *(const float4*)(cb + ch);
            float4 a = conv4(xb, tseq, ch, wX, bX);
            xv[g*4+0] = a.x; xv[g*4+1] = a.y; xv[g*4+2] = a.z; xv[g*4+3] = a.w;
        }
    }
    const float Dh = Dvec[h];
    __half hv[16];
#pragma unroll
    for (int j = 0; j < 16; j++) {
        int ch = chbase + j;
        size_t oidx = (bt0 + l) * D_INNER + ch;
        float zd = g_xbcza[(bt0 + l) * IN_PROJ + CONV_DIM + ch] + z_bias[ch];
        float sg = zd / (1.f + __expf(-zd));
        hv[j] = __float2half_rn((g_y[oidx] + e * acc[j] + Dh * xv[j]) * sg);
    }
    size_t ob = (bt0 + l) * (size_t)D_INNER + chbase;
#pragma unroll
    for (int q = 0; q < 2; q++)
        *(uint4*)(yh + ob + q * 8) = make_uint4(
            *(uint32_t*)&hv[q*8+0], *(uint32_t*)&hv[q*8+2],
            *(uint32_t*)&hv[q*8+4], *(uint32_t*)&hv[q*8+6]);
}

// ---------------------------------------------------------------------------
extern "C" void kernel_launch(void* const* d_in, const int* in_sizes, int n_in,
                              void* d_out, int out_size)
{
    const float* u      = (const float*)d_in[0];
    const float* W_in   = (const float*)d_in[1];
    const float* conv_w = (const float*)d_in[2];
    const float* conv_b = (const float*)d_in[3];
    const float* z_bias = (const float*)d_in[4];
    const float* Dvec   = (const float*)d_in[5];
    const float* W_out  = (const float*)d_in[6];
    float* out = (float*)d_out;

    float *p_xbcza = nullptr;
    __half *p_a, *p_w1, *p_w2;
    cudaGetSymbolAddress((void**)&p_xbcza, g_xbcza);
    cudaGetSymbolAddress((void**)&p_a, g_act);
    cudaGetSymbolAddress((void**)&p_w1, g_w1);
    cudaGetSymbolAddress((void**)&p_w2, g_w2);

    static int attr_set = 0;
    if (!attr_set) {
        cudaFuncSetAttribute(gemm_hmma,
            cudaFuncAttributeMaxDynamicSharedMemorySize, GEMM_SMEM);
        size_t csm = (64*CTS + 64*CTS + 128*XSS + 128*CTS + 2*CHUNK_) * sizeof(float);
        cudaFuncSetAttribute(chunk_kernel,
            cudaFuncAttributeMaxDynamicSharedMemorySize, (int)csm);
        attr_set = 1;
    }

    // fp16 conversions
    cvt_f16<<<(BT*1024)/1024, 256>>>(u, p_a, BT*1024, BT*1024);
    cvt_f16<<<(IN_PROJ_PAD*1024)/1024, 256>>>(W_in, p_w1,
                                              IN_PROJ*1024, IN_PROJ_PAD*1024);
    cvt_f16<<<(1024*1024)/1024, 256>>>(W_out, p_w2, 1024*1024, 1024*1024);

    // in-proj
    {
        dim3 grid(IN_PROJ_PAD / 128, BT / 128);
        gemm_hmma<<<grid, 256, GEMM_SMEM>>>(p_a, p_w1,
                                            p_xbcza, D_MODEL, IN_PROJ, IN_PROJ);
    }
    // chunk (conv fused)
    {
        size_t csm = (64*CTS + 64*CTS + 128*XSS + 128*CTS + 2*CHUNK_) * sizeof(float);
        dim3 grid(NV_, NC_, BATCH);
        chunk_kernel<<<grid, 256, csm>>>(conv_w, conv_b);
    }
    scan_kernel<<<BATCH * NV_, 512>>>();
    // y_off (conv fused, fp16 output)
    {
        dim3 grid(NV_, NC_, BATCH);
        yoff_kernel<<<grid, 256>>>(conv_w, conv_b, z_bias, Dvec, p_a);
    }
    // out-proj (consumes yoff's fp16 output directly)
    {
        dim3 grid(D_MODEL / 128, BT / 128);
        gemm_hmma<<<grid, 256, GEMM_SMEM>>>(p_a, p_w2,
                                            out, D_INNER, D_MODEL, D_MODEL);
    }
}

// round 17
// speedup vs baseline: 2.9135x; 1.0525x over previous
#include <cuda_runtime.h>
#include <cuda_fp16.h>
#include <cuda_bf16.h>
#include <cstdint>
#include <cstddef>

#define D_MODEL   1024
#define D_INNER   1024
#define NQK       32
#define NV_       32
#define DSTATE    64
#define DCONV     4
#define CHUNK_    128
#define CONV_DIM  5120
#define HEADDIM   32
#define IN_PROJ   6176
#define IN_PROJ_PAD 6272
#define BATCH     2
#define SEQ       8192
#define BT        16384
#define NC_       64

// ---- scratch (device globals) ----
__device__ __align__(16) float g_xbcza[(size_t)BT * IN_PROJ];
__device__ __align__(16) float g_y[(size_t)BT * D_INNER];
__device__ __align__(16) float g_states[(size_t)BATCH * NC_ * NV_ * HEADDIM * DSTATE];
__device__ __align__(16) float g_prevs [(size_t)BATCH * NC_ * NV_ * HEADDIM * DSTATE];
__device__ __align__(16) float g_acum  [(size_t)BATCH * NC_ * NV_ * CHUNK_];
__device__ __align__(16) float g_dc    [BATCH * NC_ * NV_];
__device__ __align__(16) __half g_act[(size_t)BT * 1024];
__device__ __align__(16) __half g_w1 [(size_t)IN_PROJ_PAD * 1024];
__device__ __align__(16) __half g_w2 [(size_t)1024 * 1024];

// ===========================================================================
// fp16 conversion (RN)
// ===========================================================================
__global__ void cvt_f16(const float* __restrict__ s,
                        __half* __restrict__ d,
                        int n_real, int n_total)
{
    int i = (blockIdx.x * 256 + threadIdx.x) * 4;
    if (i >= n_total) return;
    __half h[4];
    if (i < n_real) {
        float4 v = *(const float4*)(s + i);
        h[0] = __float2half_rn(v.x); h[1] = __float2half_rn(v.y);
        h[2] = __float2half_rn(v.z); h[3] = __float2half_rn(v.w);
    } else {
        h[0] = h[1] = h[2] = h[3] = __float2half_rn(0.f);
    }
    *(uint2*)(d + i) = make_uint2(*(uint32_t*)&h[0], *(uint32_t*)&h[2]);
}

// ===========================================================================
// shared helpers
// ===========================================================================
__device__ __forceinline__ uint32_t smem_u32(const void* p) {
    uint32_t a;
    asm("{ .reg .u64 t; cvta.to.shared.u64 t, %1; cvt.u32.u64 %0, t; }"
        : "=r"(a) : "l"(p));
    return a;
}
__device__ __forceinline__ uint32_t sw128(uint32_t off) {
    return off ^ ((off >> 3) & 0x70);
}
__device__ __forceinline__ void ldmat4(uint32_t& r0, uint32_t& r1,
                                       uint32_t& r2, uint32_t& r3, uint32_t a) {
    asm volatile("ldmatrix.sync.aligned.m8n8.x4.shared.b16 {%0,%1,%2,%3}, [%4];"
                 : "=r"(r0), "=r"(r1), "=r"(r2), "=r"(r3) : "r"(a));
}
__device__ __forceinline__ void mma16816h(float* c, const uint32_t* a,
                                          uint32_t b0, uint32_t b1) {
    asm volatile(
        "mma.sync.aligned.m16n8k16.row.col.f32.f16.f16.f32 "
        "{%0,%1,%2,%3}, {%4,%5,%6,%7}, {%8,%9}, {%0,%1,%2,%3};"
        : "+f"(c[0]), "+f"(c[1]), "+f"(c[2]), "+f"(c[3])
        : "r"(a[0]), "r"(a[1]), "r"(a[2]), "r"(a[3]), "r"(b0), "r"(b1));
}
__device__ __forceinline__ void mma16816b(float* c, const uint32_t* a,
                                          uint32_t b0, uint32_t b1) {
    asm volatile(
        "mma.sync.aligned.m16n8k16.row.col.f32.bf16.bf16.f32 "
        "{%0,%1,%2,%3}, {%4,%5,%6,%7}, {%8,%9}, {%0,%1,%2,%3};"
        : "+f"(c[0]), "+f"(c[1]), "+f"(c[2]), "+f"(c[3])
        : "r"(a[0]), "r"(a[1]), "r"(a[2]), "r"(a[3]), "r"(b0), "r"(b1));
}
__device__ __forceinline__ void cp16(uint32_t dst, const void* src) {
    asm volatile("cp.async.cg.shared.global [%0], [%1], 16;"
                 :: "r"(dst), "l"(src));
}

// ===========================================================================
// HMMA fp16 single-pass GEMM (NT) — R16 best: 256 thr, 2 CTAs/SM, 64x32 warps
// ===========================================================================
__device__ __forceinline__ void load_tile_async256h(
    const __half* __restrict__ g, int row0, int K, int k0,
    uint32_t sbase, int tid)
{
#pragma unroll
    for (int j = 0; j < 4; j++) {
        int u = tid + 256 * j;
        int row = u >> 3, cg = u & 7;
        uint32_t off = (uint32_t)(row * 128 + cg * 16);
        cp16(sbase + sw128(off), g + (size_t)(row0 + row) * K + k0 + cg * 8);
    }
}

#define STAGE_SZ 32768u
#define GEMM_SMEM (2 * 32768)
__global__ __launch_bounds__(256, 2)
void gemm_hmma(const __half* __restrict__ A,
               const __half* __restrict__ B,
               float* __restrict__ C, int K, int Nreal, int ldc)
{
    extern __shared__ char sm[];
    const uint32_t s0 = smem_u32(sm);
    const int tid = threadIdx.x;
    const int wid = tid >> 5, lid = tid & 31;
    const int wm = wid & 1, wn = wid >> 1;
    const int m0 = blockIdx.y * 128, n0 = blockIdx.x * 128;

    float acc[4][4][4];
#pragma unroll
    for (int i = 0; i < 4; i++)
#pragma unroll
        for (int j = 0; j < 4; j++)
#pragma unroll
            for (int q = 0; q < 4; q++) acc[i][j][q] = 0.f;

    const int lrow = lid & 15;
    const int lkb  = (lid >> 4) * 16;
    const int NKC = K >> 6;

    {
        load_tile_async256h(A, m0, K, 0, s0,         tid);
        load_tile_async256h(B, n0, K, 0, s0 + 16384, tid);
        asm volatile("cp.async.commit_group;");
    }

    for (int kc = 0; kc < NKC; kc++) {
        if (kc + 1 < NKC) {
            uint32_t base = s0 + ((kc + 1) & 1) * STAGE_SZ;
            int k0 = (kc + 1) << 6;
            load_tile_async256h(A, m0, K, k0, base,         tid);
            load_tile_async256h(B, n0, K, k0, base + 16384, tid);
            asm volatile("cp.async.commit_group;");
            asm volatile("cp.async.wait_group 1;");
        } else {
            asm volatile("cp.async.wait_group 0;");
        }
        __syncthreads();

        const uint32_t sA = s0 + (kc & 1) * STAGE_SZ;
        const uint32_t sB = sA + 16384;
#pragma unroll
        for (int ks = 0; ks < 4; ks++) {
            const int kb = ks * 32 + lkb;
            uint32_t bh[2][4];
#pragma unroll
            for (int g2 = 0; g2 < 2; g2++) {
                uint32_t off = sw128((uint32_t)((wn * 32 + g2 * 16 + lrow) * 128 + kb));
                ldmat4(bh[g2][0], bh[g2][1], bh[g2][2], bh[g2][3], sB + off);
            }
#pragma unroll
            for (int mi = 0; mi < 4; mi++) {
                uint32_t ah[4];
                uint32_t off = sw128((uint32_t)((wm * 64 + mi * 16 + lrow) * 128 + kb));
                ldmat4(ah[0], ah[1], ah[2], ah[3], sA + off);
#pragma unroll
                for (int ni = 0; ni < 4; ni++) {
                    const int g2 = ni >> 1, pt = ni & 1;
                    mma16816h(acc[mi][ni], ah, bh[g2][pt], bh[g2][pt + 2]);
                }
            }
        }
        __syncthreads();
    }

    const int crow = lid >> 2, ccol = (lid & 3) * 2;
#pragma unroll
    for (int mi = 0; mi < 4; mi++) {
#pragma unroll
        for (int ni = 0; ni < 4; ni++) {
            int n = n0 + wn * 32 + ni * 8 + ccol;
            if (n >= Nreal) continue;
            int m = m0 + wm * 64 + mi * 16 + crow;
            *(float2*)(C + (size_t)m * ldc + n) =
                make_float2(acc[mi][ni][0], acc[mi][ni][1]);
            *(float2*)(C + (size_t)(m + 8) * ldc + n) =
                make_float2(acc[mi][ni][2], acc[mi][ni][3]);
        }
    }
}

// ---------------------------------------------------------------------------
// Fused conv helper: bias, taps k=0..3 order.
// ---------------------------------------------------------------------------
__device__ __forceinline__ float4 conv4(const float* __restrict__ xb,
                                        int tseq, int ch,
                                        const float w[4][4], float4 bias)
{
    float4 a = bias;
#pragma unroll
    for (int k = 0; k < 4; k++) {
        int tt = tseq - 3 + k;
        if (tt >= 0) {
            float4 v = *(const float4*)(xb + (size_t)tt * IN_PROJ + ch);
            a.x += w[0][k] * v.x; a.y += w[1][k] * v.y;
            a.z += w[2][k] * v.z; a.w += w[3][k] * v.w;
        }
    }
    return a;
}
__device__ __forceinline__ void load_w4(const float* __restrict__ cw, int ch,
                                        float w[4][4])
{
#pragma unroll
    for (int i = 0; i < 4; i++)
#pragma unroll
        for (int k = 0; k < 4; k++) w[i][k] = cw[(ch + i) * 4 + k];
}
__device__ __forceinline__ void split_store(char* base, uint32_t off,
                                            uint32_t tile_stride, float4 v)
{
    float a4[4] = {v.x, v.y, v.z, v.w};
    __nv_bfloat16 hh[4], ll[4];
#pragma unroll
    for (int j = 0; j < 4; j++) {
        hh[j] = __float2bfloat16(a4[j]);
        ll[j] = __float2bfloat16(a4[j] - __bfloat162float(hh[j]));
    }
    *(uint2*)(base + off) = make_uint2(*(uint32_t*)&hh[0], *(uint32_t*)&hh[2]);
    *(uint2*)(base + tile_stride + off) =
        make_uint2(*(uint32_t*)&ll[0], *(uint32_t*)&ll[2]);
}

// ---------------------------------------------------------------------------
// Chunk kernel: conv fused; G via 3-pass split-bf16 HMMA (R11-verified code).
// smem: Btm 33.8K + Xs 16.9K + Ps 67.6K + 1K + bf16 tiles 64K = 184.8 KB.
// ---------------------------------------------------------------------------
#define CTS 132
#define XSS 33
#define CK_F (64*CTS + 128*XSS + 128*CTS + 2*CHUNK_)
#define CK_BF_OFF (CK_F * 4)
#define CK_TILE 16384u
#define CHUNK_SMEM (CK_BF_OFF + 4 * 16384)
__global__ __launch_bounds__(256, 1) void chunk_kernel(
    const float* __restrict__ cw, const float* __restrict__ cb)
{
    extern __shared__ float smf[];
    float* Btm  = smf;                    // [64][132] fp32 (n-major, for states)
    float* Xs   = Btm + 64 * CTS;         // [128][33]
    float* Ps   = Xs + 128 * XSS;         // [128][132]
    float* acum = Ps + 128 * CTS;         // [128]
    float* darr = acum + CHUNK_;          // [128]
    char* smb = (char*)smf;
    const uint32_t sBase = smem_u32(smb);
    const uint32_t sCH = sBase + CK_BF_OFF;            // C hi  [128 l][64 n]
    const uint32_t sCL = sCH + CK_TILE;                // C lo
    const uint32_t sBH = sCL + CK_TILE;                // B hi  [128 s][64 n]
    const uint32_t sBL = sBH + CK_TILE;                // B lo

    const int tid = threadIdx.x;
    const int wid = tid >> 5, lid = tid & 31;
    const int h = blockIdx.x, c = blockIdx.y, b = blockIdx.z;
    const size_t bt0 = (size_t)b * SEQ + (size_t)c * CHUNK_;
    const int chunk_id = (b * NC_ + c) * NV_ + h;
    const float* xb = g_xbcza + (size_t)b * SEQ * IN_PROJ;
    const int tseq0 = c * CHUNK_;

    if (tid < 128) {
        float a = g_xbcza[(bt0 + tid) * IN_PROJ + (CONV_DIM + D_INNER) + h];
        darr[tid] = (a > 20.f) ? a : log1pf(expf(a));
    }
    __syncthreads();
    if (tid < 32) {
        float v0 = darr[tid*4+0], v1 = darr[tid*4+1];
        float v2 = darr[tid*4+2], v3 = darr[tid*4+3];
        float s1 = v0+v1, s2 = s1+v2, s3 = s2+v3;
        float t = s3;
#pragma unroll
        for (int o = 1; o < 32; o <<= 1) {
            float u2 = __shfl_up_sync(0xffffffffu, t, o);
            if (tid >= o) t += u2;
        }
        float base = t - s3;
        acum[tid*4+0] = -(base+v0); acum[tid*4+1] = -(base+s1);
        acum[tid*4+2] = -(base+s2); acum[tid*4+3] = -(base+s3);
    }
    __syncthreads();
    const float alast = acum[127];
    if (tid < 128) {
        darr[tid] = __expf(alast - acum[tid]);
        g_acum[(size_t)chunk_id * CHUNK_ + tid] = acum[tid];
    }
    if (tid == 0) g_dc[chunk_id] = __expf(alast);

    // C (bf16 hi/lo only) and B (fp32 n-major + bf16 hi/lo), conv fused
    {
        const int col = (tid & 15) * 4;
        const int chC = D_INNER + NQK*DSTATE + h*DSTATE + col;
        const int chB = D_INNER + h*DSTATE + col;
        float wC[4][4], wB[4][4];
        load_w4(cw, chC, wC);
        load_w4(cw, chB, wB);
        float4 bC = *(const float4*)(cb + chC);
        float4 bB = *(const float4*)(cb + chB);
#pragma unroll
        for (int pass = 0; pass < 8; pass++) {
            int r = pass * 16 + (tid >> 4);
            float4 aC = conv4(xb, tseq0 + r, chC, wC, bC);
            float4 aB = conv4(xb, tseq0 + r, chB, wB, bB);
            uint32_t off = sw128((uint32_t)(r * 128 + col * 2));
            split_store(smb + CK_BF_OFF, off, CK_TILE, aC);
            split_store(smb + CK_BF_OFF + 2 * CK_TILE, off, CK_TILE, aB);
            Btm[(col+0)*CTS + r] = aB.x; Btm[(col+1)*CTS + r] = aB.y;
            Btm[(col+2)*CTS + r] = aB.z; Btm[(col+3)*CTS + r] = aB.w;
        }
    }
    // X fp32 (conv fused)
    {
        const int col = (tid & 7) * 4;
        const int chX = h*HEADDIM + col;
        float wX[4][4];
        load_w4(cw, chX, wX);
        float4 bX = *(const float4*)(cb + chX);
#pragma unroll
        for (int pass = 0; pass < 4; pass++) {
            int r = pass * 32 + (tid >> 3);
            float4 aX = conv4(xb, tseq0 + r, chX, wX, bX);
            Xs[r*XSS + col+0] = aX.x; Xs[r*XSS + col+1] = aX.y;
            Xs[r*XSS + col+2] = aX.z; Xs[r*XSS + col+3] = aX.w;
        }
    }
    __syncthreads();

    // --- G = C.B^T via HMMA (3-pass split-bf16), K=64; mask -> Ps ---
    {
        const int wm = wid & 1, wn = wid >> 1;   // 2 x 4 warps over 128x128
        float gacc[4][4][4];
#pragma unroll
        for (int i = 0; i < 4; i++)
#pragma unroll
            for (int j = 0; j < 4; j++)
#pragma unroll
                for (int q = 0; q < 4; q++) gacc[i][j][q] = 0.f;

        const int lrow = lid & 15;
        const int lkb  = (lid >> 4) * 16;
#pragma unroll
        for (int ks = 0; ks < 4; ks++) {
            const int kb = ks * 32 + lkb;
            uint32_t bhf[2][4], blf[2][4];
#pragma unroll
            for (int g2 = 0; g2 < 2; g2++) {
                uint32_t off = sw128((uint32_t)((wn * 32 + g2 * 16 + lrow) * 128 + kb));
                ldmat4(bhf[g2][0], bhf[g2][1], bhf[g2][2], bhf[g2][3], sBH + off);
                ldmat4(blf[g2][0], blf[g2][1], blf[g2][2], blf[g2][3], sBL + off);
            }
#pragma unroll
            for (int mi = 0; mi < 4; mi++) {
                uint32_t ah[4], al4[4];
                uint32_t off = sw128((uint32_t)((wm * 64 + mi * 16 + lrow) * 128 + kb));
                ldmat4(ah[0], ah[1], ah[2], ah[3], sCH + off);
                ldmat4(al4[0], al4[1], al4[2], al4[3], sCL + off);
#pragma unroll
                for (int ni = 0; ni < 4; ni++) {
                    const int g2 = ni >> 1, pt = ni & 1;
                    mma16816b(gacc[mi][ni], ah, bhf[g2][pt], bhf[g2][pt + 2]);
                    mma16816b(gacc[mi][ni], ah, blf[g2][pt], blf[g2][pt + 2]);
                    mma16816b(gacc[mi][ni], al4, bhf[g2][pt], bhf[g2][pt + 2]);
                }
            }
        }

        const int crow = lid >> 2, ccol = (lid & 3) * 2;
        float alr[8], asc[8];
#pragma unroll
        for (int mi = 0; mi < 4; mi++) {
            alr[mi*2]   = acum[wm*64 + mi*16 + crow];
            alr[mi*2+1] = acum[wm*64 + mi*16 + crow + 8];
        }
#pragma unroll
        for (int ni = 0; ni < 4; ni++) {
            asc[ni*2]   = acum[wn*32 + ni*8 + ccol];
            asc[ni*2+1] = acum[wn*32 + ni*8 + ccol + 1];
        }
#pragma unroll
        for (int mi = 0; mi < 4; mi++) {
#pragma unroll
            for (int ni = 0; ni < 4; ni++) {
                int l0 = wm*64 + mi*16 + crow;
                int s0q = wn*32 + ni*8 + ccol;
                float v00 = (s0q   <= l0)   ? gacc[mi][ni][0] * __expf(alr[mi*2]   - asc[ni*2])   : 0.f;
                float v01 = (s0q+1 <= l0)   ? gacc[mi][ni][1] * __expf(alr[mi*2]   - asc[ni*2+1]) : 0.f;
                float v10 = (s0q   <= l0+8) ? gacc[mi][ni][2] * __expf(alr[mi*2+1] - asc[ni*2])   : 0.f;
                float v11 = (s0q+1 <= l0+8) ? gacc[mi][ni][3] * __expf(alr[mi*2+1] - asc[ni*2+1]) : 0.f;
                *(float2*)&Ps[l0*CTS + s0q]     = make_float2(v00, v01);
                *(float2*)&Ps[(l0+8)*CTS + s0q] = make_float2(v10, v11);
            }
        }
    }
    __syncthreads();

    // --- Y_diag = Ps @ X (fp32 scalar, unchanged) ---
    {
        const int lq = tid >> 3, pq = tid & 7;
        float acc[4][4] = {};
        for (int s = 0; s < 128; s++) {
            float bf0 = Xs[s*XSS + pq*4+0];
            float bf1 = Xs[s*XSS + pq*4+1];
            float bf2 = Xs[s*XSS + pq*4+2];
            float bf3 = Xs[s*XSS + pq*4+3];
#pragma unroll
            for (int i = 0; i < 4; i++) {
                float a = Ps[(lq*4+i)*CTS + s];
                acc[i][0] += a*bf0; acc[i][1] += a*bf1;
                acc[i][2] += a*bf2; acc[i][3] += a*bf3;
            }
        }
#pragma unroll
        for (int i = 0; i < 4; i++) {
            size_t row = (bt0 + lq*4 + i) * D_INNER + h*HEADDIM + pq*4;
            *(float4*)&g_y[row] = make_float4(acc[i][0],acc[i][1],acc[i][2],acc[i][3]);
        }
    }

    // --- states (fp32 scalar, unchanged) ---
    {
        const int n  = tid >> 2;
        const int pg = tid & 3;
        float acc[8] = {};
        for (int l = 0; l < 128; l++) {
            float bv = Btm[n*CTS + l] * darr[l];
#pragma unroll
            for (int j = 0; j < 8; j++) acc[j] += bv * Xs[l*XSS + pg*8 + j];
        }
        size_t base = (size_t)chunk_id * (HEADDIM * DSTATE);
#pragma unroll
        for (int j = 0; j < 8; j++)
            g_states[base + (size_t)(pg*8 + j) * DSTATE + n] = acc[j];
    }
}

// ---------------------------------------------------------------------------
__global__ void scan_kernel()
{
    const int bh = blockIdx.x;
    const int b = bh >> 5, h = bh & 31;
    const int e = threadIdx.x * 4;
    float4 S = make_float4(0.f,0.f,0.f,0.f);
    for (int c = 0; c < NC_; c++) {
        const int cid = (b * NC_ + c) * NV_ + h;
        size_t base = (size_t)cid * (HEADDIM * DSTATE) + e;
        *(float4*)&g_prevs[base] = S;
        float4 st = *(const float4*)&g_states[base];
        float d = g_dc[cid];
        S.x = S.x*d + st.x; S.y = S.y*d + st.y;
        S.z = S.z*d + st.z; S.w = S.w*d + st.w;
    }
}

// ---------------------------------------------------------------------------
// Y_off + D*x + SiLU gating (conv fused); writes fp16 y for out-proj.
// ---------------------------------------------------------------------------
__global__ __launch_bounds__(256) void yoff_kernel(
    const float* __restrict__ cw, const float* __restrict__ cb,
    const float* __restrict__ z_bias, const float* __restrict__ Dvec,
    __half* __restrict__ yh)
{
    __shared__ float Cs[128 * 65];
    __shared__ float Pv[32 * 65];
    __shared__ float ea[128];
    const int tid = threadIdx.x;
    const int h = blockIdx.x, c = blockIdx.y, b = blockIdx.z;
    const size_t bt0 = (size_t)b * SEQ + (size_t)c * CHUNK_;
    const int chunk_id = (b * NC_ + c) * NV_ + h;
    const float* xb = g_xbcza + (size_t)b * SEQ * IN_PROJ;
    const int tseq0 = c * CHUNK_;

    if (tid < 128) ea[tid] = __expf(g_acum[(size_t)chunk_id * CHUNK_ + tid]);

    {
        const int col = (tid & 15) * 4;
        const int chC = D_INNER + NQK*DSTATE + h*DSTATE + col;
        float wC[4][4];
        load_w4(cw, chC, wC);
        float4 bC = *(const float4*)(cb + chC);
#pragma unroll
        for (int pass = 0; pass < 8; pass++) {
            int r = pass * 16 + (tid >> 4);
            float4 v = conv4(xb, tseq0 + r, chC, wC, bC);
            Cs[r*65 + col+0] = v.x; Cs[r*65 + col+1] = v.y;
            Cs[r*65 + col+2] = v.z; Cs[r*65 + col+3] = v.w;
        }
    }
    size_t pbase = (size_t)chunk_id * (HEADDIM * DSTATE);
#pragma unroll
    for (int pass = 0; pass < 2; pass++) {
        int idx = pass * 256 + tid;
        int p = idx >> 4, col = (idx & 15) * 4;
        float4 v = *(const float4*)(g_prevs + pbase + (size_t)p * DSTATE + col);
        Pv[p*65 + col+0] = v.x; Pv[p*65 + col+1] = v.y;
        Pv[p*65 + col+2] = v.z; Pv[p*65 + col+3] = v.w;
    }
    __syncthreads();

    const int l = tid >> 1;
    const int p0 = (tid & 1) * 16;
    const float e = ea[l];
    float acc[16];
#pragma unroll
    for (int j = 0; j < 16; j++) acc[j] = 0.f;
    for (int n = 0; n < 64; n++) {
        float cv = Cs[l*65 + n];
#pragma unroll
        for (int j = 0; j < 16; j++) acc[j] += cv * Pv[(p0+j)*65 + n];
    }
    const int chbase = h * HEADDIM + p0;
    float xv[16];
    {
        const int tseq = tseq0 + l;
#pragma unroll
        for (int g = 0; g < 4; g++) {
            int ch = chbase + g * 4;
            float wX[4][4];
            load_w4(cw, ch, wX);
            float4 bX = *(const float4*)(cb + ch);
            float4 a = conv4(xb, tseq, ch, wX, bX);
            xv[g*4+0] = a.x; xv[g*4+1] = a.y; xv[g*4+2] = a.z; xv[g*4+3] = a.w;
        }
    }
    const float Dh = Dvec[h];
    __half hv[16];
#pragma unroll
    for (int j = 0; j < 16; j++) {
        int ch = chbase + j;
        size_t oidx = (bt0 + l) * D_INNER + ch;
        float zd = g_xbcza[(bt0 + l) * IN_PROJ + CONV_DIM + ch] + z_bias[ch];
        float sg = zd / (1.f + __expf(-zd));
        hv[j] = __float2half_rn((g_y[oidx] + e * acc[j] + Dh * xv[j]) * sg);
    }
    size_t ob = (bt0 + l) * (size_t)D_INNER + chbase;
#pragma unroll
    for (int q = 0; q < 2; q++)
        *(uint4*)(yh + ob + q * 8) = make_uint4(
            *(uint32_t*)&hv[q*8+0], *(uint32_t*)&hv[q*8+2],
            *(uint32_t*)&hv[q*8+4], *(uint32_t*)&hv[q*8+6]);
}

// ---------------------------------------------------------------------------
extern "C" void kernel_launch(void* const* d_in, const int* in_sizes, int n_in,
                              void* d_out, int out_size)
{
    const float* u      = (const float*)d_in[0];
    const float* W_in   = (const float*)d_in[1];
    const float* conv_w = (const float*)d_in[2];
    const float* conv_b = (const float*)d_in[3];
    const float* z_bias = (const float*)d_in[4];
    const float* Dvec   = (const float*)d_in[5];
    const float* W_out  = (const float*)d_in[6];
    float* out = (float*)d_out;

    float *p_xbcza = nullptr;
    __half *p_a, *p_w1, *p_w2;
    cudaGetSymbolAddress((void**)&p_xbcza, g_xbcza);
    cudaGetSymbolAddress((void**)&p_a, g_act);
    cudaGetSymbolAddress((void**)&p_w1, g_w1);
    cudaGetSymbolAddress((void**)&p_w2, g_w2);

    static int attr_set = 0;
    if (!attr_set) {
        cudaFuncSetAttribute(gemm_hmma,
            cudaFuncAttributeMaxDynamicSharedMemorySize, GEMM_SMEM);
        cudaFuncSetAttribute(chunk_kernel,
            cudaFuncAttributeMaxDynamicSharedMemorySize, CHUNK_SMEM);
        attr_set = 1;
    }

    // fp16 conversions
    cvt_f16<<<(BT*1024)/1024, 256>>>(u, p_a, BT*1024, BT*1024);
    cvt_f16<<<(IN_PROJ_PAD*1024)/1024, 256>>>(W_in, p_w1,
                                              IN_PROJ*1024, IN_PROJ_PAD*1024);
    cvt_f16<<<(1024*1024)/1024, 256>>>(W_out, p_w2, 1024*1024, 1024*1024);

    // in-proj
    {
        dim3 grid(IN_PROJ_PAD / 128, BT / 128);
        gemm_hmma<<<grid, 256, GEMM_SMEM>>>(p_a, p_w1,
                                            p_xbcza, D_MODEL, IN_PROJ, IN_PROJ);
    }
    // chunk (conv fused, HMMA G)
    {
        dim3 grid(NV_, NC_, BATCH);
        chunk_kernel<<<grid, 256, CHUNK_SMEM>>>(conv_w, conv_b);
    }
    scan_kernel<<<BATCH * NV_, 512>>>();
    // y_off (conv fused, fp16 output)
    {
        dim3 grid(NV_, NC_, BATCH);
        yoff_kernel<<<grid, 256>>>(conv_w, conv_b, z_bias, Dvec, p_a);
    }
    // out-proj
    {
        dim3 grid(D_MODEL / 128, BT / 128);
        gemm_hmma<<<grid, 256, GEMM_SMEM>>>(p_a, p_w2,
                                            out, D_INNER, D_MODEL, D_MODEL);
    }
}